// round 8
// baseline (speedup 1.0000x reference)
#include <cuda_runtime.h>
#include <cuda_bf16.h>
#include <math.h>
#include <stdint.h>

#define B_   2
#define S_   2048
#define D_   1024
#define H_   16
#define DK_  64
#define DFF_ 4096
#define M_   (B_ * S_)

// ---------------------------------------------------------------------------
// Scratch
// ---------------------------------------------------------------------------
__device__ float g_ffn[M_ * 2 * DFF_];   // reused as bf16 silu hi/lo storage
__device__ float g_x2 [M_ * D_];
__device__ float2 g_rope[S_ * 32];

#define ASZ (16u * 1048576u)
#define WSZ (16u * 1048576u)
__device__ __nv_bfloat16 g_sh[ASZ];
__device__ __nv_bfloat16 g_sl[ASZ];
__device__ __nv_bfloat16 g_wh[WSZ];
__device__ __nv_bfloat16 g_wl[WSZ];

// weight offsets (elements); Q,K,V contiguous; W1,W3 interleaved at OW_1
#define OW_Q  0u
#define OW_K  1048576u
#define OW_V  2097152u
#define OW_O  3145728u
#define OW_1  4194304u
#define OW_2  12582912u
// activation regions in g_sh/g_sl
#define OQ_   0u
#define OK_   4194304u
#define OV_   8388608u
#define OA_   12582912u   // h-split before qkv GEMM; attn output after

// ---------------------------------------------------------------------------
// helpers
// ---------------------------------------------------------------------------
__device__ __forceinline__ uint32_t smem_u32(const void* p) {
    uint32_t a;
    asm("{ .reg .u64 t; cvta.to.shared.u64 t, %1; cvt.u32.u64 %0, t; }"
        : "=r"(a) : "l"(p));
    return a;
}
__device__ __forceinline__ void cp16(uint32_t dst, const void* src) {
    asm volatile("cp.async.cg.shared.global [%0], [%1], 16;"
                 :: "r"(dst), "l"(src));
}
__device__ __forceinline__ void ldm4(uint32_t* r, uint32_t a) {
    asm volatile("ldmatrix.sync.aligned.m8n8.x4.shared.b16 {%0,%1,%2,%3}, [%4];"
                 : "=r"(r[0]), "=r"(r[1]), "=r"(r[2]), "=r"(r[3]) : "r"(a));
}
__device__ __forceinline__ void ldm4t(uint32_t* r, uint32_t a) {
    asm volatile("ldmatrix.sync.aligned.m8n8.x4.trans.shared.b16 {%0,%1,%2,%3}, [%4];"
                 : "=r"(r[0]), "=r"(r[1]), "=r"(r[2]), "=r"(r[3]) : "r"(a));
}
__device__ __forceinline__ void mma16816(float* c, const uint32_t* a,
                                         uint32_t b0, uint32_t b1) {
    asm volatile(
        "mma.sync.aligned.m16n8k16.row.col.f32.bf16.bf16.f32 "
        "{%0,%1,%2,%3}, {%4,%5,%6,%7}, {%8,%9}, {%0,%1,%2,%3};"
        : "+f"(c[0]), "+f"(c[1]), "+f"(c[2]), "+f"(c[3])
        : "r"(a[0]), "r"(a[1]), "r"(a[2]), "r"(a[3]), "r"(b0), "r"(b1));
}
__device__ __forceinline__ uint32_t packbf(float lo, float hi) {
    uint32_t r;
    asm("cvt.rn.bf16x2.f32 %0, %1, %2;" : "=r"(r) : "f"(hi), "f"(lo));
    return r;
}
__device__ __forceinline__ void split1(float v, float& rh, float& rl) {
    __nv_bfloat16 hb = __float2bfloat16(v);
    rh = __bfloat162float(hb);
    rl = v - rh;
}
__device__ __forceinline__ void split4_pack(const float4 v, uint2& uh, uint2& ul) {
    float h0, l0, h1, l1, h2, l2, h3, l3;
    split1(v.x, h0, l0); split1(v.y, h1, l1);
    split1(v.z, h2, l2); split1(v.w, h3, l3);
    uh.x = packbf(h0, h1); uh.y = packbf(h2, h3);
    ul.x = packbf(l0, l1); ul.y = packbf(l2, l3);
}

// ---------------------------------------------------------------------------
// weight split, MLP=4
// ---------------------------------------------------------------------------
__global__ void wsplit_kernel(const float* __restrict__ s,
                              __nv_bfloat16* __restrict__ hi,
                              __nv_bfloat16* __restrict__ lo, int n4) {
    int q = n4 >> 2;
    int t = blockIdx.x * blockDim.x + threadIdx.x;
    if (t >= q) return;
    float4 v0 = ((const float4*)s)[t];
    float4 v1 = ((const float4*)s)[t + q];
    float4 v2 = ((const float4*)s)[t + 2 * q];
    float4 v3 = ((const float4*)s)[t + 3 * q];
    uint2 h0, l0, h1, l1, h2, l2, h3, l3;
    split4_pack(v0, h0, l0); split4_pack(v1, h1, l1);
    split4_pack(v2, h2, l2); split4_pack(v3, h3, l3);
    ((uint2*)hi)[t]         = h0; ((uint2*)lo)[t]         = l0;
    ((uint2*)hi)[t + q]     = h1; ((uint2*)lo)[t + q]     = l1;
    ((uint2*)hi)[t + 2 * q] = h2; ((uint2*)lo)[t + 2 * q] = l2;
    ((uint2*)hi)[t + 3 * q] = h3; ((uint2*)lo)[t + 3 * q] = l3;
}

// w1/w3 split with row interleave: out row 2i = w1 row i, 2i+1 = w3 row i
__global__ void wsplit13_kernel(const float* __restrict__ w1,
                                const float* __restrict__ w3,
                                __nv_bfloat16* __restrict__ hi,
                                __nv_bfloat16* __restrict__ lo) {
    int t = blockIdx.x * blockDim.x + threadIdx.x;   // float4 over w1 (1M)
    if (t >= DFF_ * D_ / 4) return;
    int i = t >> 8, c = t & 255;                      // row, float4-col
    float4 a = ((const float4*)w1)[t];
    float4 b = ((const float4*)w3)[t];
    uint2 ha, la, hb, lb;
    split4_pack(a, ha, la);
    split4_pack(b, hb, lb);
    ((uint2*)hi)[(2 * i) * 256 + c]     = ha;
    ((uint2*)lo)[(2 * i) * 256 + c]     = la;
    ((uint2*)hi)[(2 * i + 1) * 256 + c] = hb;
    ((uint2*)lo)[(2 * i + 1) * 256 + c] = lb;
}

// ---------------------------------------------------------------------------
// shared GEMM mainloop: acc[2][8][4] = A[128,K] @ B[128,K]^T (3-pass split)
// ---------------------------------------------------------------------------
#define LDSP    80
#define ARRSZ   10240
#define STAGE   40960
#define MG_SMEM (2 * STAGE)

__device__ __forceinline__ void gemm_mainloop(
    uint32_t sb, char* smx, int tid,
    const __nv_bfloat16* pAh, const __nv_bfloat16* pAl,
    const __nv_bfloat16* pBh, const __nv_bfloat16* pBl,
    int K, float acc[2][8][4]) {
    int wid = tid >> 5, lane = tid & 31;
    int wm = (wid & 3) * 32, wn = (wid >> 2) * 64;
    int nch = K >> 5;
    int jrow0 = tid >> 2;
    int jrow1 = 64 + (tid >> 2);
    int kb = (tid & 3);

#define LOADCHUNK(c, s)                                                        \
    {                                                                          \
        int k0 = (c) << 5;                                                     \
        uint32_t stg = sb + (s) * STAGE;                                       \
        {                                                                      \
            uint32_t db = stg + jrow0 * LDSP + kb * 16;                        \
            size_t go = (size_t)jrow0 * K + k0 + kb * 8;                       \
            cp16(db, pAh + go);                                                \
            cp16(db + ARRSZ, pAl + go);                                        \
            cp16(db + 2 * ARRSZ, pBh + go);                                    \
            cp16(db + 3 * ARRSZ, pBl + go);                                    \
        }                                                                      \
        {                                                                      \
            uint32_t db = stg + jrow1 * LDSP + kb * 16;                        \
            size_t go = (size_t)jrow1 * K + k0 + kb * 8;                       \
            cp16(db, pAh + go);                                                \
            cp16(db + ARRSZ, pAl + go);                                        \
            cp16(db + 2 * ARRSZ, pBh + go);                                    \
            cp16(db + 3 * ARRSZ, pBl + go);                                    \
        }                                                                      \
        asm volatile("cp.async.commit_group;");                                \
    }

    LOADCHUNK(0, 0)

    for (int c = 0; c < nch; c++) {
        int s = c & 1;
        if (c + 1 < nch) {
            LOADCHUNK(c + 1, s ^ 1)
            asm volatile("cp.async.wait_group 1;");
        } else {
            asm volatile("cp.async.wait_group 0;");
        }
        __syncthreads();

        uint32_t stg = sb + s * STAGE;
#pragma unroll
        for (int ks = 0; ks < 2; ks++) {
            uint32_t ar = stg + (wm + (lane & 15)) * LDSP
                        + (ks * 16 + (lane >> 4) * 8) * 2;
            uint32_t ahf[2][4], alf[2][4];
            ldm4(ahf[0], ar);
            ldm4(ahf[1], ar + 16 * LDSP);
            ldm4(alf[0], ar + ARRSZ);
            ldm4(alf[1], ar + ARRSZ + 16 * LDSP);
            uint32_t br = stg + 2 * ARRSZ
                        + (wn + (lane & 7) + ((lane >> 4) & 1) * 8) * LDSP
                        + (ks * 16 + ((lane >> 3) & 1) * 8) * 2;
#pragma unroll
            for (int g = 0; g < 4; g++) {
                uint32_t bh4[4], bl4[4];
                ldm4(bh4, br + g * 16 * LDSP);
                ldm4(bl4, br + g * 16 * LDSP + ARRSZ);
                mma16816(acc[0][2 * g],     ahf[0], bh4[0], bh4[1]);
                mma16816(acc[0][2 * g + 1], ahf[0], bh4[2], bh4[3]);
                mma16816(acc[1][2 * g],     ahf[1], bh4[0], bh4[1]);
                mma16816(acc[1][2 * g + 1], ahf[1], bh4[2], bh4[3]);
                mma16816(acc[0][2 * g],     ahf[0], bl4[0], bl4[1]);
                mma16816(acc[0][2 * g + 1], ahf[0], bl4[2], bl4[3]);
                mma16816(acc[1][2 * g],     ahf[1], bl4[0], bl4[1]);
                mma16816(acc[1][2 * g + 1], ahf[1], bl4[2], bl4[3]);
                mma16816(acc[0][2 * g],     alf[0], bh4[0], bh4[1]);
                mma16816(acc[0][2 * g + 1], alf[0], bh4[2], bh4[3]);
                mma16816(acc[1][2 * g],     alf[1], bh4[0], bh4[1]);
                mma16816(acc[1][2 * g + 1], alf[1], bh4[2], bh4[3]);
            }
        }
        __syncthreads();
    }
}

// ---------------------------------------------------------------------------
// generic GEMM: C fp32 (+R)
// ---------------------------------------------------------------------------
__global__ __launch_bounds__(256, 2) void mma_gemm_kernel(
    const __nv_bfloat16* __restrict__ Ah, const __nv_bfloat16* __restrict__ Al,
    const __nv_bfloat16* __restrict__ Bh, const __nv_bfloat16* __restrict__ Bl,
    const float* __restrict__ R, float* __restrict__ C,
    int M, int N, int K) {
    extern __shared__ char smx[];
    uint32_t sb = smem_u32(smx);
    int tid = threadIdx.x, wid = tid >> 5, lane = tid & 31;
    int bm = blockIdx.y * 128, bn = blockIdx.x * 128;
    int wm = (wid & 3) * 32, wn = (wid >> 2) * 64;

    float acc[2][8][4];
#pragma unroll
    for (int i = 0; i < 2; i++)
#pragma unroll
        for (int j = 0; j < 8; j++)
#pragma unroll
            for (int t = 0; t < 4; t++) acc[i][j][t] = 0.f;

    gemm_mainloop(sb, smx, tid, Ah + (size_t)bm * K, Al + (size_t)bm * K,
                  Bh + (size_t)bn * K, Bl + (size_t)bn * K, K, acc);

#pragma unroll
    for (int mt = 0; mt < 2; mt++) {
        int m0 = bm + wm + mt * 16 + (lane >> 2);
#pragma unroll
        for (int nt = 0; nt < 8; nt++) {
            int n0 = bn + wn + nt * 8 + (lane & 3) * 2;
            float2 v0 = make_float2(acc[mt][nt][0], acc[mt][nt][1]);
            float2 v1 = make_float2(acc[mt][nt][2], acc[mt][nt][3]);
            if (R) {
                float2 r0 = *(const float2*)(R + (size_t)m0 * N + n0);
                float2 r1 = *(const float2*)(R + (size_t)(m0 + 8) * N + n0);
                v0.x += r0.x; v0.y += r0.y;
                v1.x += r1.x; v1.y += r1.y;
            }
            *(float2*)(C + (size_t)m0 * N + n0) = v0;
            *(float2*)(C + (size_t)(m0 + 8) * N + n0) = v1;
        }
    }
}

// ---------------------------------------------------------------------------
// qkv GEMM: N=3072 fixed; epilogue applies RoPE to q/k pairs, splits to
// bf16 hi/lo, writes [b,h,s,dk]-layout q/k/v regions directly.
// ---------------------------------------------------------------------------
__global__ __launch_bounds__(256, 2) void mma_gemm_qkv_kernel(
    const __nv_bfloat16* __restrict__ Ah, const __nv_bfloat16* __restrict__ Al,
    const __nv_bfloat16* __restrict__ Bh, const __nv_bfloat16* __restrict__ Bl,
    const float2* __restrict__ tab,
    __nv_bfloat16* __restrict__ osh, __nv_bfloat16* __restrict__ osl) {
    extern __shared__ char smx[];
    uint32_t sb = smem_u32(smx);
    int tid = threadIdx.x, wid = tid >> 5, lane = tid & 31;
    int bm = blockIdx.y * 128, bn = blockIdx.x * 128;
    int wm = (wid & 3) * 32, wn = (wid >> 2) * 64;
    const int K = D_;

    float acc[2][8][4];
#pragma unroll
    for (int i = 0; i < 2; i++)
#pragma unroll
        for (int j = 0; j < 8; j++)
#pragma unroll
            for (int t = 0; t < 4; t++) acc[i][j][t] = 0.f;

    gemm_mainloop(sb, smx, tid, Ah + (size_t)bm * K, Al + (size_t)bm * K,
                  Bh + (size_t)bn * K, Bl + (size_t)bn * K, K, acc);

#pragma unroll
    for (int nt = 0; nt < 8; nt++) {
        int n0 = bn + wn + nt * 8 + (lane & 3) * 2;    // even
        int sec = n0 >> 10;                             // 0=q 1=k 2=v
        int d = n0 & 1023;
        int hh = d >> 6;
        int dk = d & 63;
        uint32_t obase = sec * 4194304u;
#pragma unroll
        for (int mt = 0; mt < 2; mt++) {
            int m0 = bm + wm + mt * 16 + (lane >> 2);
#pragma unroll
            for (int rr = 0; rr < 2; rr++) {
                int m = m0 + rr * 8;
                int s = m & (S_ - 1);
                int b = m >> 11;
                float e = acc[mt][nt][rr * 2], o = acc[mt][nt][rr * 2 + 1];
                if (sec < 2) {
                    float2 cs = tab[(s << 5) + (dk >> 1)];
                    float e2 = cs.x * e - cs.y * o;
                    o = cs.y * e + cs.x * o;
                    e = e2;
                }
                float eh, el, oh2, ol2;
                split1(e, eh, el); split1(o, oh2, ol2);
                size_t off = obase + ((size_t)(b * H_ + hh) * S_ + s) * DK_ + dk;
                *(uint32_t*)(osh + off) = packbf(eh, oh2);
                *(uint32_t*)(osl + off) = packbf(el, ol2);
            }
        }
    }
}

// ---------------------------------------------------------------------------
// w1|w3 GEMM with fused SwiGLU: N=8192 interleaved (even=u, odd=g).
// Epilogue writes silu bf16 hi/lo [M, DFF].
// ---------------------------------------------------------------------------
__global__ __launch_bounds__(256, 2) void mma_gemm_swiglu_kernel(
    const __nv_bfloat16* __restrict__ Ah, const __nv_bfloat16* __restrict__ Al,
    const __nv_bfloat16* __restrict__ Bh, const __nv_bfloat16* __restrict__ Bl,
    __nv_bfloat16* __restrict__ hi, __nv_bfloat16* __restrict__ lo) {
    extern __shared__ char smx[];
    uint32_t sb = smem_u32(smx);
    int tid = threadIdx.x, wid = tid >> 5, lane = tid & 31;
    int bm = blockIdx.y * 128, bn = blockIdx.x * 128;
    int wm = (wid & 3) * 32, wn = (wid >> 2) * 64;
    const int K = D_;

    float acc[2][8][4];
#pragma unroll
    for (int i = 0; i < 2; i++)
#pragma unroll
        for (int j = 0; j < 8; j++)
#pragma unroll
            for (int t = 0; t < 4; t++) acc[i][j][t] = 0.f;

    gemm_mainloop(sb, smx, tid, Ah + (size_t)bm * K, Al + (size_t)bm * K,
                  Bh + (size_t)bn * K, Bl + (size_t)bn * K, K, acc);

#pragma unroll
    for (int mt = 0; mt < 2; mt++) {
        int m0 = bm + wm + mt * 16 + (lane >> 2);
#pragma unroll
        for (int nt = 0; nt < 8; nt++) {
            int f0 = (bn + wn + nt * 8 + (lane & 3) * 2) >> 1;
#pragma unroll
            for (int rr = 0; rr < 2; rr++) {
                int m = m0 + rr * 8;
                float u = acc[mt][nt][rr * 2];
                float g = acc[mt][nt][rr * 2 + 1];
                float r = u * (1.0f / (1.0f + __expf(-u))) * g;
                float rh, rl;
                split1(r, rh, rl);
                size_t off = (size_t)m * DFF_ + f0;
                hi[off] = __float2bfloat16(rh);
                lo[off] = __float2bfloat16(rl);
            }
        }
    }
}

// ---------------------------------------------------------------------------
// RoPE table (double precision; fast-math-proof)
// ---------------------------------------------------------------------------
__global__ void rope_table_kernel(float2* __restrict__ tab) {
    int idx = blockIdx.x * blockDim.x + threadIdx.x;
    if (idx >= S_ * 32) return;
    int s = idx >> 5;
    int i = idx & 31;
    double invf = exp2(-(double)(2 * i) * (13.287712379549449 / 64.0));
    double ang = (double)s * invf;
    double sd, cd;
    sincos(ang, &sd, &cd);
    tab[idx] = make_float2((float)cd, (float)sd);
}

// ---------------------------------------------------------------------------
// RMSNorm fused with bf16 split
// ---------------------------------------------------------------------------
__global__ __launch_bounds__(256) void rmsnorm_split_kernel(
    const float* __restrict__ x, const float* __restrict__ w,
    __nv_bfloat16* __restrict__ hi, __nv_bfloat16* __restrict__ lo) {
    int row = blockIdx.x;
    const float4* xr = (const float4*)(x + (size_t)row * D_);
    int i = threadIdx.x;
    float4 xv = xr[i];
    float ss = xv.x * xv.x + xv.y * xv.y + xv.z * xv.z + xv.w * xv.w;
#pragma unroll
    for (int off = 16; off > 0; off >>= 1)
        ss += __shfl_xor_sync(0xffffffffu, ss, off);
    __shared__ float red[8];
    __shared__ float s_inv;
    if ((threadIdx.x & 31) == 0) red[threadIdx.x >> 5] = ss;
    __syncthreads();
    if (threadIdx.x == 0) {
        float t = 0.f;
#pragma unroll
        for (int j = 0; j < 8; j++) t += red[j];
        s_inv = rsqrtf(t * (1.0f / D_) + 1e-5f);
    }
    __syncthreads();
    float inv = s_inv;
    float4 wv = ((const float4*)w)[i];
    float4 r;
    r.x = inv * xv.x * wv.x;
    r.y = inv * xv.y * wv.y;
    r.z = inv * xv.z * wv.z;
    r.w = inv * xv.w * wv.w;
    uint2 uh, ul;
    split4_pack(r, uh, ul);
    ((uint2*)(hi + (size_t)row * D_))[i] = uh;
    ((uint2*)(lo + (size_t)row * D_))[i] = ul;
}

// ---------------------------------------------------------------------------
// HMMA causal flash attention; writes bf16 hi/lo split.
// ---------------------------------------------------------------------------
#define AP    144
#define SQH   0
#define SQL   9216
#define SKH   18432
#define SKL   27648
#define SVH   36864
#define SVL   46080
#define AT_SMEM 55296

__global__ __launch_bounds__(128, 2) void attn_mma_kernel(
    const __nv_bfloat16* __restrict__ sh_in, const __nv_bfloat16* __restrict__ sl_in,
    __nv_bfloat16* __restrict__ oh, __nv_bfloat16* __restrict__ ol) {
    extern __shared__ char smx[];
    uint32_t sb = smem_u32(smx);
    int tid = threadIdx.x, w = tid >> 5, lane = tid & 31;
    int qt = gridDim.x - 1 - blockIdx.x;
    int h = blockIdx.y, b = blockIdx.z;
    size_t base = (size_t)(b * H_ + h) * S_;
    int s0 = qt * 64;

    const __nv_bfloat16* qh = sh_in + OQ_;
    const __nv_bfloat16* ql = sl_in + OQ_;
    const __nv_bfloat16* kh = sh_in + OK_;
    const __nv_bfloat16* kl = sl_in + OK_;
    const __nv_bfloat16* vh = sh_in + OV_;
    const __nv_bfloat16* vl = sl_in + OV_;

#pragma unroll
    for (int i = 0; i < 4; i++) {
        int idx = i * 128 + tid;
        int row = idx >> 3, c = idx & 7;
        size_t go = (base + s0 + row) * DK_ + c * 8;
        cp16(sb + SQH + row * AP + c * 16, qh + go);
        cp16(sb + SQL + row * AP + c * 16, ql + go);
    }
    asm volatile("cp.async.commit_group;");
    asm volatile("cp.async.wait_group 0;");
    __syncthreads();

    uint32_t qfh[4][4], qfl[4][4];
#pragma unroll
    for (int ks = 0; ks < 4; ks++) {
        uint32_t ar = sb + SQH + (16 * w + (lane & 15)) * AP
                    + (ks * 16 + (lane >> 4) * 8) * 2;
        ldm4(qfh[ks], ar);
        ldm4(qfl[ks], ar + (SQL - SQH));
    }

    float oacc[8][4];
#pragma unroll
    for (int j = 0; j < 8; j++)
#pragma unroll
        for (int t = 0; t < 4; t++) oacc[j][t] = 0.f;
    float m0 = -INFINITY, m1 = -INFINITY, l0 = 0.f, l1 = 0.f;
    int q0 = s0 + 16 * w + (lane >> 2);

    for (int kvt = 0; kvt <= qt; kvt++) {
        int kv0 = kvt * 64;
        __syncthreads();
#pragma unroll
        for (int i = 0; i < 4; i++) {
            int idx = i * 128 + tid;
            int row = idx >> 3, c = idx & 7;
            size_t go = (base + kv0 + row) * DK_ + c * 8;
            uint32_t db = sb + row * AP + c * 16;
            cp16(db + SKH, kh + go);
            cp16(db + SKL, kl + go);
            cp16(db + SVH, vh + go);
            cp16(db + SVL, vl + go);
        }
        asm volatile("cp.async.commit_group;");
        asm volatile("cp.async.wait_group 0;");
        __syncthreads();

        float sacc[8][4];
#pragma unroll
        for (int j = 0; j < 8; j++)
#pragma unroll
            for (int t = 0; t < 4; t++) sacc[j][t] = 0.f;
#pragma unroll
        for (int ks = 0; ks < 4; ks++) {
            uint32_t br = sb + SKH + ((lane & 7) + ((lane >> 4) & 1) * 8) * AP
                        + (ks * 16 + ((lane >> 3) & 1) * 8) * 2;
#pragma unroll
            for (int g = 0; g < 4; g++) {
                uint32_t bh4[4], bl4[4];
                ldm4(bh4, br + g * 16 * AP);
                ldm4(bl4, br + g * 16 * AP + (SKL - SKH));
                mma16816(sacc[2 * g],     qfh[ks], bh4[0], bh4[1]);
                mma16816(sacc[2 * g + 1], qfh[ks], bh4[2], bh4[3]);
                mma16816(sacc[2 * g],     qfh[ks], bl4[0], bl4[1]);
                mma16816(sacc[2 * g + 1], qfh[ks], bl4[2], bl4[3]);
                mma16816(sacc[2 * g],     qfl[ks], bh4[0], bh4[1]);
                mma16816(sacc[2 * g + 1], qfl[ks], bh4[2], bh4[3]);
            }
        }
#pragma unroll
        for (int j = 0; j < 8; j++)
#pragma unroll
            for (int t = 0; t < 4; t++) sacc[j][t] *= 0.125f;
        if (kvt == qt) {
            int cb = kv0 + 2 * (lane & 3);
#pragma unroll
            for (int j = 0; j < 8; j++) {
                int kc = cb + 8 * j;
                if (kc     > q0)     sacc[j][0] = -INFINITY;
                if (kc + 1 > q0)     sacc[j][1] = -INFINITY;
                if (kc     > q0 + 8) sacc[j][2] = -INFINITY;
                if (kc + 1 > q0 + 8) sacc[j][3] = -INFINITY;
            }
        }
        float mx0 = -INFINITY, mx1 = -INFINITY;
#pragma unroll
        for (int j = 0; j < 8; j++) {
            mx0 = fmaxf(mx0, fmaxf(sacc[j][0], sacc[j][1]));
            mx1 = fmaxf(mx1, fmaxf(sacc[j][2], sacc[j][3]));
        }
        mx0 = fmaxf(mx0, __shfl_xor_sync(0xffffffffu, mx0, 1));
        mx0 = fmaxf(mx0, __shfl_xor_sync(0xffffffffu, mx0, 2));
        mx1 = fmaxf(mx1, __shfl_xor_sync(0xffffffffu, mx1, 1));
        mx1 = fmaxf(mx1, __shfl_xor_sync(0xffffffffu, mx1, 2));
        float mn0 = fmaxf(m0, mx0), mn1 = fmaxf(m1, mx1);
        float cr0 = __expf(m0 - mn0), cr1 = __expf(m1 - mn1);
        l0 *= cr0; l1 *= cr1;
#pragma unroll
        for (int j = 0; j < 8; j++) {
            oacc[j][0] *= cr0; oacc[j][1] *= cr0;
            oacc[j][2] *= cr1; oacc[j][3] *= cr1;
        }
        uint32_t pf[4][4];
#pragma unroll
        for (int j = 0; j < 8; j++) {
            float p0 = __expf(sacc[j][0] - mn0);
            float p1 = __expf(sacc[j][1] - mn0);
            float p2 = __expf(sacc[j][2] - mn1);
            float p3 = __expf(sacc[j][3] - mn1);
            l0 += p0 + p1; l1 += p2 + p3;
            pf[j >> 1][(j & 1) * 2]     = packbf(p0, p1);
            pf[j >> 1][(j & 1) * 2 + 1] = packbf(p2, p3);
        }
        m0 = mn0; m1 = mn1;
#pragma unroll
        for (int kt = 0; kt < 4; kt++) {
            uint32_t va = sb + SVH + (kt * 16 + (lane & 15)) * AP
                        + ((lane >> 4) * 8) * 2;
#pragma unroll
            for (int gn = 0; gn < 4; gn++) {
                uint32_t vb[4];
                ldm4t(vb, va + gn * 32);
                mma16816(oacc[2 * gn],     pf[kt], vb[0], vb[1]);
                mma16816(oacc[2 * gn + 1], pf[kt], vb[2], vb[3]);
                ldm4t(vb, va + gn * 32 + (SVL - SVH));
                mma16816(oacc[2 * gn],     pf[kt], vb[0], vb[1]);
                mma16816(oacc[2 * gn + 1], pf[kt], vb[2], vb[3]);
            }
        }
    }

    l0 += __shfl_xor_sync(0xffffffffu, l0, 1);
    l0 += __shfl_xor_sync(0xffffffffu, l0, 2);
    l1 += __shfl_xor_sync(0xffffffffu, l1, 1);
    l1 += __shfl_xor_sync(0xffffffffu, l1, 2);
    float i0 = 1.f / l0, i1 = 1.f / l1;

    size_t r0 = (size_t)(b * S_ + q0) * D_ + h * DK_;
    size_t r1 = (size_t)(b * S_ + q0 + 8) * D_ + h * DK_;
#pragma unroll
    for (int j = 0; j < 8; j++) {
        int dk0 = 8 * j + 2 * (lane & 3);
        float a0 = oacc[j][0] * i0, a1 = oacc[j][1] * i0;
        float b0 = oacc[j][2] * i1, b1 = oacc[j][3] * i1;
        float h0, lo0, h1, lo1, h2, lo2, h3, lo3;
        split1(a0, h0, lo0); split1(a1, h1, lo1);
        split1(b0, h2, lo2); split1(b1, h3, lo3);
        *(uint32_t*)(oh + r0 + dk0) = packbf(h0, h1);
        *(uint32_t*)(ol + r0 + dk0) = packbf(lo0, lo1);
        *(uint32_t*)(oh + r1 + dk0) = packbf(h2, h3);
        *(uint32_t*)(ol + r1 + dk0) = packbf(lo2, lo3);
    }
}

// ---------------------------------------------------------------------------
// Launch
// ---------------------------------------------------------------------------
extern "C" void kernel_launch(void* const* d_in, const int* in_sizes, int n_in,
                              void* d_out, int out_size) {
    const float* x   = (const float*)d_in[0];
    const float* w_q = (const float*)d_in[1];
    const float* w_k = (const float*)d_in[2];
    const float* w_v = (const float*)d_in[3];
    const float* w_o = (const float*)d_in[4];
    const float* ln1 = (const float*)d_in[5];
    const float* ln2 = (const float*)d_in[6];
    const float* w1  = (const float*)d_in[7];
    const float* w2  = (const float*)d_in[8];
    const float* w3  = (const float*)d_in[9];
    float* out = (float*)d_out;

    float *ffn, *x2;
    float2* rope;
    __nv_bfloat16 *sh, *sl, *wh, *wl;
    cudaGetSymbolAddress((void**)&ffn,  g_ffn);
    cudaGetSymbolAddress((void**)&x2,   g_x2);
    cudaGetSymbolAddress((void**)&rope, g_rope);
    cudaGetSymbolAddress((void**)&sh,   g_sh);
    cudaGetSymbolAddress((void**)&sl,   g_sl);
    cudaGetSymbolAddress((void**)&wh,   g_wh);
    cudaGetSymbolAddress((void**)&wl,   g_wl);
    __nv_bfloat16* silu_h = (__nv_bfloat16*)ffn;
    __nv_bfloat16* silu_l = (__nv_bfloat16*)ffn + ASZ;

    cudaFuncSetAttribute(mma_gemm_kernel,
                         cudaFuncAttributeMaxDynamicSharedMemorySize, MG_SMEM);
    cudaFuncSetAttribute(mma_gemm_qkv_kernel,
                         cudaFuncAttributeMaxDynamicSharedMemorySize, MG_SMEM);
    cudaFuncSetAttribute(mma_gemm_swiglu_kernel,
                         cudaFuncAttributeMaxDynamicSharedMemorySize, MG_SMEM);
    cudaFuncSetAttribute(attn_mma_kernel,
                         cudaFuncAttributeMaxDynamicSharedMemorySize, AT_SMEM);

    // launches 0..4: table, qkv weight splits, rmsnorm1
    rope_table_kernel<<<(S_ * 32 + 255) / 256, 256>>>(rope);
    wsplit_kernel<<<256, 256>>>(w_q, wh + OW_Q, wl + OW_Q, 262144);
    wsplit_kernel<<<256, 256>>>(w_k, wh + OW_K, wl + OW_K, 262144);
    wsplit_kernel<<<256, 256>>>(w_v, wh + OW_V, wl + OW_V, 262144);
    rmsnorm_split_kernel<<<M_, 256>>>(x, ln1, sh + OA_, sl + OA_);

    // launch 5 (ncu target): fused qkv GEMM -> roped/split q,k,v
    mma_gemm_qkv_kernel<<<dim3(3072 / 128, M_ / 128), 256, MG_SMEM>>>(
        sh + OA_, sl + OA_, wh + OW_Q, wl + OW_Q, rope, sh, sl);

    // remaining weight splits (overlap-independent)
    wsplit_kernel<<<256, 256>>>(w_o, wh + OW_O, wl + OW_O, 262144);
    wsplit13_kernel<<<4096, 256>>>(w1, w3, wh + OW_1, wl + OW_1);
    wsplit_kernel<<<1024, 256>>>(w2, wh + OW_2, wl + OW_2, 1048576);

    // attention -> split at OA_ (h no longer needed)
    attn_mma_kernel<<<dim3(S_ / 64, H_, B_), 128, AT_SMEM>>>(sh, sl, sh + OA_, sl + OA_);

    // x2 = x + attn @ w_o^T
    mma_gemm_kernel<<<dim3(D_ / 128, M_ / 128), 256, MG_SMEM>>>(
        sh + OA_, sl + OA_, wh + OW_O, wl + OW_O, x, x2, M_, D_, D_);

    // h2 = rmsnorm(x2) -> split at 0
    rmsnorm_split_kernel<<<M_, 256>>>(x2, ln2, sh, sl);

    // fused w1|w3 GEMM + SwiGLU -> silu split (in g_ffn storage)
    mma_gemm_swiglu_kernel<<<dim3(8192 / 128, M_ / 128), 256, MG_SMEM>>>(
        sh, sl, wh + OW_1, wl + OW_1, silu_h, silu_l);

    // out = x2 + silu @ w2^T
    mma_gemm_kernel<<<dim3(D_ / 128, M_ / 128), 256, MG_SMEM>>>(
        silu_h, silu_l, wh + OW_2, wl + OW_2, x2, out, M_, D_, DFF_);
}

// round 9
// speedup vs baseline: 1.3781x; 1.3781x over previous
#include <cuda_runtime.h>
#include <cuda_bf16.h>
#include <cuda_fp16.h>
#include <math.h>
#include <stdint.h>

#define B_   2
#define S_   2048
#define D_   1024
#define H_   16
#define DK_  64
#define DFF_ 4096
#define M_   (B_ * S_)

typedef __half hf;

// ---------------------------------------------------------------------------
// Scratch
// ---------------------------------------------------------------------------
__device__ float g_ffn[M_ * 2 * DFF_];   // reused as fp16 silu storage
__device__ float g_x2 [M_ * D_];
__device__ float2 g_rope[S_ * 32];

#define ASZ (16u * 1048576u)
#define WSZ (16u * 1048576u)
__device__ __nv_bfloat16 g_sh[ASZ];   // bf16 q/k/v hi + fp16 activation regions
__device__ __nv_bfloat16 g_sl[ASZ];   // bf16 q/k/v lo
__device__ hf g_wh[WSZ];              // fp16 weight hi
__device__ hf g_wl[WSZ];              // fp16 weight lo

// weight offsets (elements); Q,K,V contiguous; W1,W3 interleaved at OW_1
#define OW_Q  0u
#define OW_K  1048576u
#define OW_V  2097152u
#define OW_O  3145728u
#define OW_1  4194304u
#define OW_2  12582912u
// activation regions in g_sh/g_sl
#define OQ_   0u
#define OK_   4194304u
#define OV_   8388608u
#define OA_   12582912u   // fp16 h before qkv GEMM; fp16 attn out after

// ---------------------------------------------------------------------------
// helpers
// ---------------------------------------------------------------------------
__device__ __forceinline__ uint32_t smem_u32(const void* p) {
    uint32_t a;
    asm("{ .reg .u64 t; cvta.to.shared.u64 t, %1; cvt.u32.u64 %0, t; }"
        : "=r"(a) : "l"(p));
    return a;
}
__device__ __forceinline__ void cp16(uint32_t dst, const void* src) {
    asm volatile("cp.async.cg.shared.global [%0], [%1], 16;"
                 :: "r"(dst), "l"(src));
}
__device__ __forceinline__ void ldm4(uint32_t* r, uint32_t a) {
    asm volatile("ldmatrix.sync.aligned.m8n8.x4.shared.b16 {%0,%1,%2,%3}, [%4];"
                 : "=r"(r[0]), "=r"(r[1]), "=r"(r[2]), "=r"(r[3]) : "r"(a));
}
__device__ __forceinline__ void ldm4t(uint32_t* r, uint32_t a) {
    asm volatile("ldmatrix.sync.aligned.m8n8.x4.trans.shared.b16 {%0,%1,%2,%3}, [%4];"
                 : "=r"(r[0]), "=r"(r[1]), "=r"(r[2]), "=r"(r[3]) : "r"(a));
}
// bf16 mma (attention)
__device__ __forceinline__ void mma16816(float* c, const uint32_t* a,
                                         uint32_t b0, uint32_t b1) {
    asm volatile(
        "mma.sync.aligned.m16n8k16.row.col.f32.bf16.bf16.f32 "
        "{%0,%1,%2,%3}, {%4,%5,%6,%7}, {%8,%9}, {%0,%1,%2,%3};"
        : "+f"(c[0]), "+f"(c[1]), "+f"(c[2]), "+f"(c[3])
        : "r"(a[0]), "r"(a[1]), "r"(a[2]), "r"(a[3]), "r"(b0), "r"(b1));
}
// fp16 mma (GEMMs)
__device__ __forceinline__ void mmah(float* c, const uint32_t* a,
                                     uint32_t b0, uint32_t b1) {
    asm volatile(
        "mma.sync.aligned.m16n8k16.row.col.f32.f16.f16.f32 "
        "{%0,%1,%2,%3}, {%4,%5,%6,%7}, {%8,%9}, {%0,%1,%2,%3};"
        : "+f"(c[0]), "+f"(c[1]), "+f"(c[2]), "+f"(c[3])
        : "r"(a[0]), "r"(a[1]), "r"(a[2]), "r"(a[3]), "r"(b0), "r"(b1));
}
__device__ __forceinline__ uint32_t packbf(float lo, float hi) {
    uint32_t r;
    asm("cvt.rn.bf16x2.f32 %0, %1, %2;" : "=r"(r) : "f"(hi), "f"(lo));
    return r;
}
__device__ __forceinline__ uint32_t packh2(float lo, float hi) {
    uint32_t r;
    asm("cvt.rn.f16x2.f32 %0, %1, %2;" : "=r"(r) : "f"(hi), "f"(lo));
    return r;
}
__device__ __forceinline__ void split1(float v, float& rh, float& rl) {
    __nv_bfloat16 hb = __float2bfloat16(v);
    rh = __bfloat162float(hb);
    rl = v - rh;
}
// fp16 split
__device__ __forceinline__ void split1h(float v, hf& h, float& l) {
    h = __float2half_rn(v);
    l = v - __half2float(h);
}
__device__ __forceinline__ void split4h_pack(const float4 v, uint2& uh, uint2& ul) {
    hf h0, h1, h2, h3;
    float l0, l1, l2, l3;
    split1h(v.x, h0, l0); split1h(v.y, h1, l1);
    split1h(v.z, h2, l2); split1h(v.w, h3, l3);
    uh.x = (uint32_t)__half_as_ushort(h0) | ((uint32_t)__half_as_ushort(h1) << 16);
    uh.y = (uint32_t)__half_as_ushort(h2) | ((uint32_t)__half_as_ushort(h3) << 16);
    ul.x = packh2(l0, l1);
    ul.y = packh2(l2, l3);
}

// ---------------------------------------------------------------------------
// weight splits (fp16 hi/lo)
// ---------------------------------------------------------------------------
// qkv: three 1M-element weights, one launch
__global__ void wsplit3_kernel(const float* __restrict__ a,
                               const float* __restrict__ b,
                               const float* __restrict__ c,
                               hf* __restrict__ hi, hf* __restrict__ lo) {
    int t = blockIdx.x * blockDim.x + threadIdx.x;
    if (t >= 262144) return;
    uint2 uh, ul;
    split4h_pack(((const float4*)a)[t], uh, ul);
    ((uint2*)hi)[t] = uh; ((uint2*)lo)[t] = ul;
    split4h_pack(((const float4*)b)[t], uh, ul);
    ((uint2*)hi)[262144 + t] = uh; ((uint2*)lo)[262144 + t] = ul;
    split4h_pack(((const float4*)c)[t], uh, ul);
    ((uint2*)hi)[524288 + t] = uh; ((uint2*)lo)[524288 + t] = ul;
}

__global__ void wsplit_kernel(const float* __restrict__ s,
                              hf* __restrict__ hi, hf* __restrict__ lo, int n4) {
    int q = n4 >> 2;
    int t = blockIdx.x * blockDim.x + threadIdx.x;
    if (t >= q) return;
#pragma unroll
    for (int i = 0; i < 4; i++) {
        uint2 uh, ul;
        split4h_pack(((const float4*)s)[t + i * q], uh, ul);
        ((uint2*)hi)[t + i * q] = uh;
        ((uint2*)lo)[t + i * q] = ul;
    }
}

// w1/w3 row-interleaved split
__global__ void wsplit13_kernel(const float* __restrict__ w1,
                                const float* __restrict__ w3,
                                hf* __restrict__ hi, hf* __restrict__ lo) {
    int t = blockIdx.x * blockDim.x + threadIdx.x;
    if (t >= DFF_ * D_ / 4) return;
    int i = t >> 8, c = t & 255;
    uint2 ha, la, hb, lb;
    split4h_pack(((const float4*)w1)[t], ha, la);
    split4h_pack(((const float4*)w3)[t], hb, lb);
    ((uint2*)hi)[(2 * i) * 256 + c]     = ha;
    ((uint2*)lo)[(2 * i) * 256 + c]     = la;
    ((uint2*)hi)[(2 * i + 1) * 256 + c] = hb;
    ((uint2*)lo)[(2 * i + 1) * 256 + c] = lb;
}

// ---------------------------------------------------------------------------
// fp16 2-pass GEMM mainloop: acc = A[128,K](fp16) @ (Bh+Bl)[128,K]^T
// smem: A | Bh | Bl, 80B pitch, double buffered
// ---------------------------------------------------------------------------
#define LDSP    80
#define ARRSZ   10240
#define STAGE   30720
#define MG_SMEM (2 * STAGE)

__device__ __forceinline__ void gemm_mainloop(
    uint32_t sb, int tid,
    const hf* pA, const hf* pBh, const hf* pBl,
    int K, float acc[2][8][4]) {
    int wid = tid >> 5, lane = tid & 31;
    int wm = (wid & 3) * 32, wn = (wid >> 2) * 64;
    int nch = K >> 5;
    int jrow0 = tid >> 2;
    int jrow1 = 64 + jrow0;
    int kb = (tid & 3);

#define LOADCHUNK(c, s)                                                        \
    {                                                                          \
        int k0 = (c) << 5;                                                     \
        uint32_t stg = sb + (s) * STAGE;                                       \
        {                                                                      \
            uint32_t db = stg + jrow0 * LDSP + kb * 16;                        \
            size_t go = (size_t)jrow0 * K + k0 + kb * 8;                       \
            cp16(db, pA + go);                                                 \
            cp16(db + ARRSZ, pBh + go);                                        \
            cp16(db + 2 * ARRSZ, pBl + go);                                    \
        }                                                                      \
        {                                                                      \
            uint32_t db = stg + jrow1 * LDSP + kb * 16;                        \
            size_t go = (size_t)jrow1 * K + k0 + kb * 8;                       \
            cp16(db, pA + go);                                                 \
            cp16(db + ARRSZ, pBh + go);                                        \
            cp16(db + 2 * ARRSZ, pBl + go);                                    \
        }                                                                      \
        asm volatile("cp.async.commit_group;");                                \
    }

    LOADCHUNK(0, 0)

    for (int c = 0; c < nch; c++) {
        int s = c & 1;
        if (c + 1 < nch) {
            LOADCHUNK(c + 1, s ^ 1)
            asm volatile("cp.async.wait_group 1;");
        } else {
            asm volatile("cp.async.wait_group 0;");
        }
        __syncthreads();

        uint32_t stg = sb + s * STAGE;
#pragma unroll
        for (int ks = 0; ks < 2; ks++) {
            uint32_t ar = stg + (wm + (lane & 15)) * LDSP
                        + (ks * 16 + (lane >> 4) * 8) * 2;
            uint32_t af[2][4];
            ldm4(af[0], ar);
            ldm4(af[1], ar + 16 * LDSP);
            uint32_t br = stg + ARRSZ
                        + (wn + (lane & 7) + ((lane >> 4) & 1) * 8) * LDSP
                        + (ks * 16 + ((lane >> 3) & 1) * 8) * 2;
#pragma unroll
            for (int g = 0; g < 4; g++) {
                uint32_t bh4[4], bl4[4];
                ldm4(bh4, br + g * 16 * LDSP);
                ldm4(bl4, br + g * 16 * LDSP + ARRSZ);
                mmah(acc[0][2 * g],     af[0], bh4[0], bh4[1]);
                mmah(acc[0][2 * g + 1], af[0], bh4[2], bh4[3]);
                mmah(acc[1][2 * g],     af[1], bh4[0], bh4[1]);
                mmah(acc[1][2 * g + 1], af[1], bh4[2], bh4[3]);
                mmah(acc[0][2 * g],     af[0], bl4[0], bl4[1]);
                mmah(acc[0][2 * g + 1], af[0], bl4[2], bl4[3]);
                mmah(acc[1][2 * g],     af[1], bl4[0], bl4[1]);
                mmah(acc[1][2 * g + 1], af[1], bl4[2], bl4[3]);
            }
        }
        __syncthreads();
    }
}

// ---------------------------------------------------------------------------
// generic GEMM: C fp32 (+R)
// ---------------------------------------------------------------------------
__global__ __launch_bounds__(256, 2) void mma_gemm_kernel(
    const hf* __restrict__ A, const hf* __restrict__ Bh, const hf* __restrict__ Bl,
    const float* __restrict__ R, float* __restrict__ C,
    int M, int N, int K) {
    extern __shared__ char smx[];
    uint32_t sb = smem_u32(smx);
    int tid = threadIdx.x, wid = tid >> 5, lane = tid & 31;
    int bm = blockIdx.y * 128, bn = blockIdx.x * 128;
    int wm = (wid & 3) * 32, wn = (wid >> 2) * 64;

    float acc[2][8][4];
#pragma unroll
    for (int i = 0; i < 2; i++)
#pragma unroll
        for (int j = 0; j < 8; j++)
#pragma unroll
            for (int t = 0; t < 4; t++) acc[i][j][t] = 0.f;

    gemm_mainloop(sb, tid, A + (size_t)bm * K,
                  Bh + (size_t)bn * K, Bl + (size_t)bn * K, K, acc);

#pragma unroll
    for (int mt = 0; mt < 2; mt++) {
        int m0 = bm + wm + mt * 16 + (lane >> 2);
#pragma unroll
        for (int nt = 0; nt < 8; nt++) {
            int n0 = bn + wn + nt * 8 + (lane & 3) * 2;
            float2 v0 = make_float2(acc[mt][nt][0], acc[mt][nt][1]);
            float2 v1 = make_float2(acc[mt][nt][2], acc[mt][nt][3]);
            if (R) {
                float2 r0 = *(const float2*)(R + (size_t)m0 * N + n0);
                float2 r1 = *(const float2*)(R + (size_t)(m0 + 8) * N + n0);
                v0.x += r0.x; v0.y += r0.y;
                v1.x += r1.x; v1.y += r1.y;
            }
            *(float2*)(C + (size_t)m0 * N + n0) = v0;
            *(float2*)(C + (size_t)(m0 + 8) * N + n0) = v1;
        }
    }
}

// ---------------------------------------------------------------------------
// qkv GEMM (N=3072): epilogue does RoPE + bf16 hi/lo split + [b,h,s,dk] repack
// ---------------------------------------------------------------------------
__global__ __launch_bounds__(256, 2) void mma_gemm_qkv_kernel(
    const hf* __restrict__ A, const hf* __restrict__ Bh, const hf* __restrict__ Bl,
    const float2* __restrict__ tab,
    __nv_bfloat16* __restrict__ osh, __nv_bfloat16* __restrict__ osl) {
    extern __shared__ char smx[];
    uint32_t sb = smem_u32(smx);
    int tid = threadIdx.x, wid = tid >> 5, lane = tid & 31;
    int bm = blockIdx.y * 128, bn = blockIdx.x * 128;
    int wm = (wid & 3) * 32, wn = (wid >> 2) * 64;
    const int K = D_;

    float acc[2][8][4];
#pragma unroll
    for (int i = 0; i < 2; i++)
#pragma unroll
        for (int j = 0; j < 8; j++)
#pragma unroll
            for (int t = 0; t < 4; t++) acc[i][j][t] = 0.f;

    gemm_mainloop(sb, tid, A + (size_t)bm * K,
                  Bh + (size_t)bn * K, Bl + (size_t)bn * K, K, acc);

#pragma unroll
    for (int nt = 0; nt < 8; nt++) {
        int n0 = bn + wn + nt * 8 + (lane & 3) * 2;
        int sec = n0 >> 10;
        int d = n0 & 1023;
        int hh = d >> 6;
        int dk = d & 63;
        uint32_t obase = sec * 4194304u;
#pragma unroll
        for (int mt = 0; mt < 2; mt++) {
            int m0 = bm + wm + mt * 16 + (lane >> 2);
#pragma unroll
            for (int rr = 0; rr < 2; rr++) {
                int m = m0 + rr * 8;
                int s = m & (S_ - 1);
                int b = m >> 11;
                float e = acc[mt][nt][rr * 2], o = acc[mt][nt][rr * 2 + 1];
                if (sec < 2) {
                    float2 cs = tab[(s << 5) + (dk >> 1)];
                    float e2 = cs.x * e - cs.y * o;
                    o = cs.y * e + cs.x * o;
                    e = e2;
                }
                float eh, el, oh2, ol2;
                split1(e, eh, el); split1(o, oh2, ol2);
                size_t off = obase + ((size_t)(b * H_ + hh) * S_ + s) * DK_ + dk;
                *(uint32_t*)(osh + off) = packbf(eh, oh2);
                *(uint32_t*)(osl + off) = packbf(el, ol2);
            }
        }
    }
}

// ---------------------------------------------------------------------------
// w1|w3 GEMM + SwiGLU: N=8192 interleaved (even=u, odd=g); writes fp16 silu
// ---------------------------------------------------------------------------
__global__ __launch_bounds__(256, 2) void mma_gemm_swiglu_kernel(
    const hf* __restrict__ A, const hf* __restrict__ Bh, const hf* __restrict__ Bl,
    hf* __restrict__ outp) {
    extern __shared__ char smx[];
    uint32_t sb = smem_u32(smx);
    int tid = threadIdx.x, wid = tid >> 5, lane = tid & 31;
    int bm = blockIdx.y * 128, bn = blockIdx.x * 128;
    int wm = (wid & 3) * 32, wn = (wid >> 2) * 64;
    const int K = D_;

    float acc[2][8][4];
#pragma unroll
    for (int i = 0; i < 2; i++)
#pragma unroll
        for (int j = 0; j < 8; j++)
#pragma unroll
            for (int t = 0; t < 4; t++) acc[i][j][t] = 0.f;

    gemm_mainloop(sb, tid, A + (size_t)bm * K,
                  Bh + (size_t)bn * K, Bl + (size_t)bn * K, K, acc);

#pragma unroll
    for (int mt = 0; mt < 2; mt++) {
        int m0 = bm + wm + mt * 16 + (lane >> 2);
#pragma unroll
        for (int nt = 0; nt < 8; nt++) {
            int f0 = (bn + wn + nt * 8 + (lane & 3) * 2) >> 1;
#pragma unroll
            for (int rr = 0; rr < 2; rr++) {
                int m = m0 + rr * 8;
                float u = acc[mt][nt][rr * 2];
                float g = acc[mt][nt][rr * 2 + 1];
                float r = u * (1.0f / (1.0f + __expf(-u))) * g;
                outp[(size_t)m * DFF_ + f0] = __float2half_rn(r);
            }
        }
    }
}

// ---------------------------------------------------------------------------
// RoPE table (double precision)
// ---------------------------------------------------------------------------
__global__ void rope_table_kernel(float2* __restrict__ tab) {
    int idx = blockIdx.x * blockDim.x + threadIdx.x;
    if (idx >= S_ * 32) return;
    int s = idx >> 5;
    int i = idx & 31;
    double invf = exp2(-(double)(2 * i) * (13.287712379549449 / 64.0));
    double ang = (double)s * invf;
    double sd, cd;
    sincos(ang, &sd, &cd);
    tab[idx] = make_float2((float)cd, (float)sd);
}

// ---------------------------------------------------------------------------
// RMSNorm -> single fp16
// ---------------------------------------------------------------------------
__global__ __launch_bounds__(256) void rmsnorm_h_kernel(
    const float* __restrict__ x, const float* __restrict__ w,
    hf* __restrict__ out) {
    int row = blockIdx.x;
    const float4* xr = (const float4*)(x + (size_t)row * D_);
    int i = threadIdx.x;
    float4 xv = xr[i];
    float ss = xv.x * xv.x + xv.y * xv.y + xv.z * xv.z + xv.w * xv.w;
#pragma unroll
    for (int off = 16; off > 0; off >>= 1)
        ss += __shfl_xor_sync(0xffffffffu, ss, off);
    __shared__ float red[8];
    __shared__ float s_inv;
    if ((threadIdx.x & 31) == 0) red[threadIdx.x >> 5] = ss;
    __syncthreads();
    if (threadIdx.x == 0) {
        float t = 0.f;
#pragma unroll
        for (int j = 0; j < 8; j++) t += red[j];
        s_inv = rsqrtf(t * (1.0f / D_) + 1e-5f);
    }
    __syncthreads();
    float inv = s_inv;
    float4 wv = ((const float4*)w)[i];
    uint2 o;
    o.x = packh2(inv * xv.x * wv.x, inv * xv.y * wv.y);
    o.y = packh2(inv * xv.z * wv.z, inv * xv.w * wv.w);
    ((uint2*)(out + (size_t)row * D_))[i] = o;
}

// ---------------------------------------------------------------------------
// HMMA causal flash attention (bf16 internals); epilogue writes single fp16
// ---------------------------------------------------------------------------
#define AP    144
#define SQH   0
#define SQL   9216
#define SKH   18432
#define SKL   27648
#define SVH   36864
#define SVL   46080
#define AT_SMEM 55296

__global__ __launch_bounds__(128, 2) void attn_mma_kernel(
    const __nv_bfloat16* __restrict__ sh_in, const __nv_bfloat16* __restrict__ sl_in,
    hf* __restrict__ oh) {
    extern __shared__ char smx[];
    uint32_t sb = smem_u32(smx);
    int tid = threadIdx.x, w = tid >> 5, lane = tid & 31;
    int qt = gridDim.x - 1 - blockIdx.x;
    int h = blockIdx.y, b = blockIdx.z;
    size_t base = (size_t)(b * H_ + h) * S_;
    int s0 = qt * 64;

    const __nv_bfloat16* qh = sh_in + OQ_;
    const __nv_bfloat16* ql = sl_in + OQ_;
    const __nv_bfloat16* kh = sh_in + OK_;
    const __nv_bfloat16* kl = sl_in + OK_;
    const __nv_bfloat16* vh = sh_in + OV_;
    const __nv_bfloat16* vl = sl_in + OV_;

#pragma unroll
    for (int i = 0; i < 4; i++) {
        int idx = i * 128 + tid;
        int row = idx >> 3, c = idx & 7;
        size_t go = (base + s0 + row) * DK_ + c * 8;
        cp16(sb + SQH + row * AP + c * 16, qh + go);
        cp16(sb + SQL + row * AP + c * 16, ql + go);
    }
    asm volatile("cp.async.commit_group;");
    asm volatile("cp.async.wait_group 0;");
    __syncthreads();

    uint32_t qfh[4][4], qfl[4][4];
#pragma unroll
    for (int ks = 0; ks < 4; ks++) {
        uint32_t ar = sb + SQH + (16 * w + (lane & 15)) * AP
                    + (ks * 16 + (lane >> 4) * 8) * 2;
        ldm4(qfh[ks], ar);
        ldm4(qfl[ks], ar + (SQL - SQH));
    }

    float oacc[8][4];
#pragma unroll
    for (int j = 0; j < 8; j++)
#pragma unroll
        for (int t = 0; t < 4; t++) oacc[j][t] = 0.f;
    float m0 = -INFINITY, m1 = -INFINITY, l0 = 0.f, l1 = 0.f;
    int q0 = s0 + 16 * w + (lane >> 2);

    for (int kvt = 0; kvt <= qt; kvt++) {
        int kv0 = kvt * 64;
        __syncthreads();
#pragma unroll
        for (int i = 0; i < 4; i++) {
            int idx = i * 128 + tid;
            int row = idx >> 3, c = idx & 7;
            size_t go = (base + kv0 + row) * DK_ + c * 8;
            uint32_t db = sb + row * AP + c * 16;
            cp16(db + SKH, kh + go);
            cp16(db + SKL, kl + go);
            cp16(db + SVH, vh + go);
            cp16(db + SVL, vl + go);
        }
        asm volatile("cp.async.commit_group;");
        asm volatile("cp.async.wait_group 0;");
        __syncthreads();

        float sacc[8][4];
#pragma unroll
        for (int j = 0; j < 8; j++)
#pragma unroll
            for (int t = 0; t < 4; t++) sacc[j][t] = 0.f;
#pragma unroll
        for (int ks = 0; ks < 4; ks++) {
            uint32_t br = sb + SKH + ((lane & 7) + ((lane >> 4) & 1) * 8) * AP
                        + (ks * 16 + ((lane >> 3) & 1) * 8) * 2;
#pragma unroll
            for (int g = 0; g < 4; g++) {
                uint32_t bh4[4], bl4[4];
                ldm4(bh4, br + g * 16 * AP);
                ldm4(bl4, br + g * 16 * AP + (SKL - SKH));
                mma16816(sacc[2 * g],     qfh[ks], bh4[0], bh4[1]);
                mma16816(sacc[2 * g + 1], qfh[ks], bh4[2], bh4[3]);
                mma16816(sacc[2 * g],     qfh[ks], bl4[0], bl4[1]);
                mma16816(sacc[2 * g + 1], qfh[ks], bl4[2], bl4[3]);
                mma16816(sacc[2 * g],     qfl[ks], bh4[0], bh4[1]);
                mma16816(sacc[2 * g + 1], qfl[ks], bh4[2], bh4[3]);
            }
        }
#pragma unroll
        for (int j = 0; j < 8; j++)
#pragma unroll
            for (int t = 0; t < 4; t++) sacc[j][t] *= 0.125f;
        if (kvt == qt) {
            int cb = kv0 + 2 * (lane & 3);
#pragma unroll
            for (int j = 0; j < 8; j++) {
                int kc = cb + 8 * j;
                if (kc     > q0)     sacc[j][0] = -INFINITY;
                if (kc + 1 > q0)     sacc[j][1] = -INFINITY;
                if (kc     > q0 + 8) sacc[j][2] = -INFINITY;
                if (kc + 1 > q0 + 8) sacc[j][3] = -INFINITY;
            }
        }
        float mx0 = -INFINITY, mx1 = -INFINITY;
#pragma unroll
        for (int j = 0; j < 8; j++) {
            mx0 = fmaxf(mx0, fmaxf(sacc[j][0], sacc[j][1]));
            mx1 = fmaxf(mx1, fmaxf(sacc[j][2], sacc[j][3]));
        }
        mx0 = fmaxf(mx0, __shfl_xor_sync(0xffffffffu, mx0, 1));
        mx0 = fmaxf(mx0, __shfl_xor_sync(0xffffffffu, mx0, 2));
        mx1 = fmaxf(mx1, __shfl_xor_sync(0xffffffffu, mx1, 1));
        mx1 = fmaxf(mx1, __shfl_xor_sync(0xffffffffu, mx1, 2));
        float mn0 = fmaxf(m0, mx0), mn1 = fmaxf(m1, mx1);
        float cr0 = __expf(m0 - mn0), cr1 = __expf(m1 - mn1);
        l0 *= cr0; l1 *= cr1;
#pragma unroll
        for (int j = 0; j < 8; j++) {
            oacc[j][0] *= cr0; oacc[j][1] *= cr0;
            oacc[j][2] *= cr1; oacc[j][3] *= cr1;
        }
        uint32_t pf[4][4];
#pragma unroll
        for (int j = 0; j < 8; j++) {
            float p0 = __expf(sacc[j][0] - mn0);
            float p1 = __expf(sacc[j][1] - mn0);
            float p2 = __expf(sacc[j][2] - mn1);
            float p3 = __expf(sacc[j][3] - mn1);
            l0 += p0 + p1; l1 += p2 + p3;
            pf[j >> 1][(j & 1) * 2]     = packbf(p0, p1);
            pf[j >> 1][(j & 1) * 2 + 1] = packbf(p2, p3);
        }
        m0 = mn0; m1 = mn1;
#pragma unroll
        for (int kt = 0; kt < 4; kt++) {
            uint32_t va = sb + SVH + (kt * 16 + (lane & 15)) * AP
                        + ((lane >> 4) * 8) * 2;
#pragma unroll
            for (int gn = 0; gn < 4; gn++) {
                uint32_t vb[4];
                ldm4t(vb, va + gn * 32);
                mma16816(oacc[2 * gn],     pf[kt], vb[0], vb[1]);
                mma16816(oacc[2 * gn + 1], pf[kt], vb[2], vb[3]);
                ldm4t(vb, va + gn * 32 + (SVL - SVH));
                mma16816(oacc[2 * gn],     pf[kt], vb[0], vb[1]);
                mma16816(oacc[2 * gn + 1], pf[kt], vb[2], vb[3]);
            }
        }
    }

    l0 += __shfl_xor_sync(0xffffffffu, l0, 1);
    l0 += __shfl_xor_sync(0xffffffffu, l0, 2);
    l1 += __shfl_xor_sync(0xffffffffu, l1, 1);
    l1 += __shfl_xor_sync(0xffffffffu, l1, 2);
    float i0 = 1.f / l0, i1 = 1.f / l1;

    size_t r0 = (size_t)(b * S_ + q0) * D_ + h * DK_;
    size_t r1 = (size_t)(b * S_ + q0 + 8) * D_ + h * DK_;
#pragma unroll
    for (int j = 0; j < 8; j++) {
        int dk0 = 8 * j + 2 * (lane & 3);
        *(uint32_t*)(oh + r0 + dk0) = packh2(oacc[j][0] * i0, oacc[j][1] * i0);
        *(uint32_t*)(oh + r1 + dk0) = packh2(oacc[j][2] * i1, oacc[j][3] * i1);
    }
}

// ---------------------------------------------------------------------------
// Launch (my launch index 3 == qkv GEMM, targeted by ncu -s 5 -c 1)
// ---------------------------------------------------------------------------
extern "C" void kernel_launch(void* const* d_in, const int* in_sizes, int n_in,
                              void* d_out, int out_size) {
    const float* x   = (const float*)d_in[0];
    const float* w_q = (const float*)d_in[1];
    const float* w_k = (const float*)d_in[2];
    const float* w_v = (const float*)d_in[3];
    const float* w_o = (const float*)d_in[4];
    const float* ln1 = (const float*)d_in[5];
    const float* ln2 = (const float*)d_in[6];
    const float* w1  = (const float*)d_in[7];
    const float* w2  = (const float*)d_in[8];
    const float* w3  = (const float*)d_in[9];
    float* out = (float*)d_out;

    float *ffn, *x2;
    float2* rope;
    __nv_bfloat16 *sh, *sl;
    hf *wh, *wl;
    cudaGetSymbolAddress((void**)&ffn,  g_ffn);
    cudaGetSymbolAddress((void**)&x2,   g_x2);
    cudaGetSymbolAddress((void**)&rope, g_rope);
    cudaGetSymbolAddress((void**)&sh,   g_sh);
    cudaGetSymbolAddress((void**)&sl,   g_sl);
    cudaGetSymbolAddress((void**)&wh,   g_wh);
    cudaGetSymbolAddress((void**)&wl,   g_wl);
    hf* hA    = (hf*)(sh + OA_);       // fp16 h / attn-out region
    hf* h2A   = (hf*)sh;               // fp16 h2 region (after q consumed)
    hf* siluA = (hf*)ffn;              // fp16 silu output

    cudaFuncSetAttribute(mma_gemm_kernel,
                         cudaFuncAttributeMaxDynamicSharedMemorySize, MG_SMEM);
    cudaFuncSetAttribute(mma_gemm_qkv_kernel,
                         cudaFuncAttributeMaxDynamicSharedMemorySize, MG_SMEM);
    cudaFuncSetAttribute(mma_gemm_swiglu_kernel,
                         cudaFuncAttributeMaxDynamicSharedMemorySize, MG_SMEM);
    cudaFuncSetAttribute(attn_mma_kernel,
                         cudaFuncAttributeMaxDynamicSharedMemorySize, AT_SMEM);

    // 0..2: table, rmsnorm1, qkv weight split
    rope_table_kernel<<<(S_ * 32 + 255) / 256, 256>>>(rope);
    rmsnorm_h_kernel<<<M_, 256>>>(x, ln1, hA);
    wsplit3_kernel<<<1024, 256>>>(w_q, w_k, w_v, wh + OW_Q, wl + OW_Q);

    // 3 (ncu target): qkv GEMM -> roped/split q,k,v (bf16 hi/lo)
    mma_gemm_qkv_kernel<<<dim3(3072 / 128, M_ / 128), 256, MG_SMEM>>>(
        hA, wh + OW_Q, wl + OW_Q, rope, sh, sl);

    // remaining weight splits
    wsplit_kernel<<<256, 256>>>(w_o, wh + OW_O, wl + OW_O, 262144);
    wsplit13_kernel<<<4096, 256>>>(w1, w3, wh + OW_1, wl + OW_1);
    wsplit_kernel<<<1024, 256>>>(w2, wh + OW_2, wl + OW_2, 1048576);

    // attention -> fp16 at OA_
    attn_mma_kernel<<<dim3(S_ / 64, H_, B_), 128, AT_SMEM>>>(sh, sl, hA);

    // x2 = x + attn @ w_o^T
    mma_gemm_kernel<<<dim3(D_ / 128, M_ / 128), 256, MG_SMEM>>>(
        hA, wh + OW_O, wl + OW_O, x, x2, M_, D_, D_);

    // h2 = rmsnorm(x2) -> fp16
    rmsnorm_h_kernel<<<M_, 256>>>(x2, ln2, h2A);

    // [u|g] GEMM + SwiGLU -> fp16 silu
    mma_gemm_swiglu_kernel<<<dim3(8192 / 128, M_ / 128), 256, MG_SMEM>>>(
        h2A, wh + OW_1, wl + OW_1, siluA);

    // out = x2 + silu @ w2^T
    mma_gemm_kernel<<<dim3(D_ / 128, M_ / 128), 256, MG_SMEM>>>(
        siluA, wh + OW_2, wl + OW_2, x2, out, M_, D_, DFF_);
}

// round 10
// speedup vs baseline: 2.0190x; 1.4651x over previous
#include <cuda_runtime.h>
#include <cuda_bf16.h>
#include <cuda_fp16.h>
#include <math.h>
#include <stdint.h>

#define B_   2
#define S_   2048
#define D_   1024
#define H_   16
#define DK_  64
#define DFF_ 4096
#define M_   (B_ * S_)

typedef __half hf;

// ---------------------------------------------------------------------------
// Scratch
// ---------------------------------------------------------------------------
__device__ float g_ffn[M_ * 2 * DFF_];   // reused as fp16 silu storage
__device__ float g_x2 [M_ * D_];
__device__ float2 g_rope[S_ * 32];

#define ASZ (16u * 1048576u)
#define WSZ (16u * 1048576u)
__device__ __nv_bfloat16 g_sh[ASZ];   // bf16 q/k/v hi + fp16 activation regions
__device__ __nv_bfloat16 g_sl[ASZ];   // bf16 q/k/v lo
__device__ hf g_w [WSZ];              // fp16 weights (single precision level)

// weight offsets; Q,K,V contiguous; W1,W3 interleaved at OW_1
#define OW_Q  0u
#define OW_O  3145728u
#define OW_1  4194304u
#define OW_2  12582912u
// activation regions in g_sh/g_sl
#define OQ_   0u
#define OK_   4194304u
#define OV_   8388608u
#define OA_   12582912u   // fp16 h before qkv GEMM; fp16 attn out after

// ---------------------------------------------------------------------------
// helpers
// ---------------------------------------------------------------------------
__device__ __forceinline__ uint32_t smem_u32(const void* p) {
    uint32_t a;
    asm("{ .reg .u64 t; cvta.to.shared.u64 t, %1; cvt.u32.u64 %0, t; }"
        : "=r"(a) : "l"(p));
    return a;
}
__device__ __forceinline__ void cp16(uint32_t dst, const void* src) {
    asm volatile("cp.async.cg.shared.global [%0], [%1], 16;"
                 :: "r"(dst), "l"(src));
}
__device__ __forceinline__ void ldm4(uint32_t* r, uint32_t a) {
    asm volatile("ldmatrix.sync.aligned.m8n8.x4.shared.b16 {%0,%1,%2,%3}, [%4];"
                 : "=r"(r[0]), "=r"(r[1]), "=r"(r[2]), "=r"(r[3]) : "r"(a));
}
__device__ __forceinline__ void ldm4t(uint32_t* r, uint32_t a) {
    asm volatile("ldmatrix.sync.aligned.m8n8.x4.trans.shared.b16 {%0,%1,%2,%3}, [%4];"
                 : "=r"(r[0]), "=r"(r[1]), "=r"(r[2]), "=r"(r[3]) : "r"(a));
}
__device__ __forceinline__ void mma16816(float* c, const uint32_t* a,
                                         uint32_t b0, uint32_t b1) {
    asm volatile(
        "mma.sync.aligned.m16n8k16.row.col.f32.bf16.bf16.f32 "
        "{%0,%1,%2,%3}, {%4,%5,%6,%7}, {%8,%9}, {%0,%1,%2,%3};"
        : "+f"(c[0]), "+f"(c[1]), "+f"(c[2]), "+f"(c[3])
        : "r"(a[0]), "r"(a[1]), "r"(a[2]), "r"(a[3]), "r"(b0), "r"(b1));
}
__device__ __forceinline__ void mmah(float* c, const uint32_t* a,
                                     uint32_t b0, uint32_t b1) {
    asm volatile(
        "mma.sync.aligned.m16n8k16.row.col.f32.f16.f16.f32 "
        "{%0,%1,%2,%3}, {%4,%5,%6,%7}, {%8,%9}, {%0,%1,%2,%3};"
        : "+f"(c[0]), "+f"(c[1]), "+f"(c[2]), "+f"(c[3])
        : "r"(a[0]), "r"(a[1]), "r"(a[2]), "r"(a[3]), "r"(b0), "r"(b1));
}
__device__ __forceinline__ uint32_t packbf(float lo, float hi) {
    uint32_t r;
    asm("cvt.rn.bf16x2.f32 %0, %1, %2;" : "=r"(r) : "f"(hi), "f"(lo));
    return r;
}
__device__ __forceinline__ uint32_t packh2(float lo, float hi) {
    uint32_t r;
    asm("cvt.rn.f16x2.f32 %0, %1, %2;" : "=r"(r) : "f"(hi), "f"(lo));
    return r;
}
__device__ __forceinline__ void split1(float v, float& rh, float& rl) {
    __nv_bfloat16 hb = __float2bfloat16(v);
    rh = __bfloat162float(hb);
    rl = v - rh;
}
__device__ __forceinline__ uint2 cvt4h(const float4 v) {
    uint2 u;
    u.x = packh2(v.x, v.y);
    u.y = packh2(v.z, v.w);
    return u;
}

// ---------------------------------------------------------------------------
// weight converts (fp32 -> fp16)
// ---------------------------------------------------------------------------
__global__ void wconv3_kernel(const float* __restrict__ a,
                              const float* __restrict__ b,
                              const float* __restrict__ c,
                              hf* __restrict__ o) {
    int t = blockIdx.x * blockDim.x + threadIdx.x;
    if (t >= 262144) return;
    ((uint2*)o)[t]          = cvt4h(((const float4*)a)[t]);
    ((uint2*)o)[262144 + t] = cvt4h(((const float4*)b)[t]);
    ((uint2*)o)[524288 + t] = cvt4h(((const float4*)c)[t]);
}

__global__ void wconv_kernel(const float* __restrict__ s, hf* __restrict__ o, int n4) {
    int q = n4 >> 2;
    int t = blockIdx.x * blockDim.x + threadIdx.x;
    if (t >= q) return;
#pragma unroll
    for (int i = 0; i < 4; i++)
        ((uint2*)o)[t + i * q] = cvt4h(((const float4*)s)[t + i * q]);
}

// w1/w3 row-interleaved convert: out row 2i = w1 row i, 2i+1 = w3 row i
__global__ void wconv13_kernel(const float* __restrict__ w1,
                               const float* __restrict__ w3,
                               hf* __restrict__ o) {
    int t = blockIdx.x * blockDim.x + threadIdx.x;
    if (t >= DFF_ * D_ / 4) return;
    int i = t >> 8, c = t & 255;
    ((uint2*)o)[(2 * i) * 256 + c]     = cvt4h(((const float4*)w1)[t]);
    ((uint2*)o)[(2 * i + 1) * 256 + c] = cvt4h(((const float4*)w3)[t]);
}

// ---------------------------------------------------------------------------
// single-pass fp16 GEMM mainloop: acc = A[128,K] @ B[128,K]^T
// smem: A | B per stage (80B pitch), 3-stage cp.async pipeline
// ---------------------------------------------------------------------------
#define LDSP    80
#define ARRSZ   10240
#define STAGE   20480
#define NSTG    3
#define MG_SMEM (NSTG * STAGE)

__device__ __forceinline__ void gemm_mainloop(
    uint32_t sb, int tid,
    const hf* pA, const hf* pB,
    int K, float acc[2][8][4]) {
    int wid = tid >> 5, lane = tid & 31;
    int wm = (wid & 3) * 32, wn = (wid >> 2) * 64;
    int nch = K >> 5;
    int jrow0 = tid >> 2;
    int jrow1 = 64 + jrow0;
    int kb = (tid & 3);

#define LOADCHUNK(c, s)                                                        \
    {                                                                          \
        int k0 = (c) << 5;                                                     \
        uint32_t stg = sb + (s) * STAGE;                                       \
        {                                                                      \
            uint32_t db = stg + jrow0 * LDSP + kb * 16;                        \
            size_t go = (size_t)jrow0 * K + k0 + kb * 8;                       \
            cp16(db, pA + go);                                                 \
            cp16(db + ARRSZ, pB + go);                                         \
        }                                                                      \
        {                                                                      \
            uint32_t db = stg + jrow1 * LDSP + kb * 16;                        \
            size_t go = (size_t)jrow1 * K + k0 + kb * 8;                       \
            cp16(db, pA + go);                                                 \
            cp16(db + ARRSZ, pB + go);                                         \
        }                                                                      \
        asm volatile("cp.async.commit_group;");                                \
    }

    LOADCHUNK(0, 0)
    LOADCHUNK(1, 1)

    for (int c = 0; c < nch; c++) {
        int s = c % NSTG;
        if (c + 2 < nch) {
            LOADCHUNK(c + 2, (c + 2) % NSTG)
            asm volatile("cp.async.wait_group 2;");
        } else {
            asm volatile("cp.async.wait_group 0;");
        }
        __syncthreads();

        uint32_t stg = sb + s * STAGE;
#pragma unroll
        for (int ks = 0; ks < 2; ks++) {
            uint32_t ar = stg + (wm + (lane & 15)) * LDSP
                        + (ks * 16 + (lane >> 4) * 8) * 2;
            uint32_t af[2][4];
            ldm4(af[0], ar);
            ldm4(af[1], ar + 16 * LDSP);
            uint32_t br = stg + ARRSZ
                        + (wn + (lane & 7) + ((lane >> 4) & 1) * 8) * LDSP
                        + (ks * 16 + ((lane >> 3) & 1) * 8) * 2;
#pragma unroll
            for (int g = 0; g < 4; g++) {
                uint32_t b4[4];
                ldm4(b4, br + g * 16 * LDSP);
                mmah(acc[0][2 * g],     af[0], b4[0], b4[1]);
                mmah(acc[0][2 * g + 1], af[0], b4[2], b4[3]);
                mmah(acc[1][2 * g],     af[1], b4[0], b4[1]);
                mmah(acc[1][2 * g + 1], af[1], b4[2], b4[3]);
            }
        }
        __syncthreads();
    }
}

// ---------------------------------------------------------------------------
// generic GEMM: C fp32 (+R)
// ---------------------------------------------------------------------------
__global__ __launch_bounds__(256, 2) void mma_gemm_kernel(
    const hf* __restrict__ A, const hf* __restrict__ Bm,
    const float* __restrict__ R, float* __restrict__ C,
    int M, int N, int K) {
    extern __shared__ char smx[];
    uint32_t sb = smem_u32(smx);
    int tid = threadIdx.x, wid = tid >> 5, lane = tid & 31;
    int bm = blockIdx.y * 128, bn = blockIdx.x * 128;
    int wm = (wid & 3) * 32, wn = (wid >> 2) * 64;

    float acc[2][8][4];
#pragma unroll
    for (int i = 0; i < 2; i++)
#pragma unroll
        for (int j = 0; j < 8; j++)
#pragma unroll
            for (int t = 0; t < 4; t++) acc[i][j][t] = 0.f;

    gemm_mainloop(sb, tid, A + (size_t)bm * K, Bm + (size_t)bn * K, K, acc);

#pragma unroll
    for (int mt = 0; mt < 2; mt++) {
        int m0 = bm + wm + mt * 16 + (lane >> 2);
#pragma unroll
        for (int nt = 0; nt < 8; nt++) {
            int n0 = bn + wn + nt * 8 + (lane & 3) * 2;
            float2 v0 = make_float2(acc[mt][nt][0], acc[mt][nt][1]);
            float2 v1 = make_float2(acc[mt][nt][2], acc[mt][nt][3]);
            if (R) {
                float2 r0 = *(const float2*)(R + (size_t)m0 * N + n0);
                float2 r1 = *(const float2*)(R + (size_t)(m0 + 8) * N + n0);
                v0.x += r0.x; v0.y += r0.y;
                v1.x += r1.x; v1.y += r1.y;
            }
            *(float2*)(C + (size_t)m0 * N + n0) = v0;
            *(float2*)(C + (size_t)(m0 + 8) * N + n0) = v1;
        }
    }
}

// ---------------------------------------------------------------------------
// qkv GEMM (N=3072): epilogue RoPE + bf16 hi/lo split + [b,h,s,dk] repack
// ---------------------------------------------------------------------------
__global__ __launch_bounds__(256, 2) void mma_gemm_qkv_kernel(
    const hf* __restrict__ A, const hf* __restrict__ Bm,
    const float2* __restrict__ tab,
    __nv_bfloat16* __restrict__ osh, __nv_bfloat16* __restrict__ osl) {
    extern __shared__ char smx[];
    uint32_t sb = smem_u32(smx);
    int tid = threadIdx.x, wid = tid >> 5, lane = tid & 31;
    int bm = blockIdx.y * 128, bn = blockIdx.x * 128;
    int wm = (wid & 3) * 32, wn = (wid >> 2) * 64;
    const int K = D_;

    float acc[2][8][4];
#pragma unroll
    for (int i = 0; i < 2; i++)
#pragma unroll
        for (int j = 0; j < 8; j++)
#pragma unroll
            for (int t = 0; t < 4; t++) acc[i][j][t] = 0.f;

    gemm_mainloop(sb, tid, A + (size_t)bm * K, Bm + (size_t)bn * K, K, acc);

#pragma unroll
    for (int nt = 0; nt < 8; nt++) {
        int n0 = bn + wn + nt * 8 + (lane & 3) * 2;
        int sec = n0 >> 10;
        int d = n0 & 1023;
        int hh = d >> 6;
        int dk = d & 63;
        uint32_t obase = sec * 4194304u;
#pragma unroll
        for (int mt = 0; mt < 2; mt++) {
            int m0 = bm + wm + mt * 16 + (lane >> 2);
#pragma unroll
            for (int rr = 0; rr < 2; rr++) {
                int m = m0 + rr * 8;
                int s = m & (S_ - 1);
                int b = m >> 11;
                float e = acc[mt][nt][rr * 2], o = acc[mt][nt][rr * 2 + 1];
                if (sec < 2) {
                    float2 cs = tab[(s << 5) + (dk >> 1)];
                    float e2 = cs.x * e - cs.y * o;
                    o = cs.y * e + cs.x * o;
                    e = e2;
                }
                float eh, el, oh2, ol2;
                split1(e, eh, el); split1(o, oh2, ol2);
                size_t off = obase + ((size_t)(b * H_ + hh) * S_ + s) * DK_ + dk;
                *(uint32_t*)(osh + off) = packbf(eh, oh2);
                *(uint32_t*)(osl + off) = packbf(el, ol2);
            }
        }
    }
}

// ---------------------------------------------------------------------------
// w1|w3 GEMM + SwiGLU: N=8192 interleaved (even=u, odd=g); writes fp16 silu
// ---------------------------------------------------------------------------
__global__ __launch_bounds__(256, 2) void mma_gemm_swiglu_kernel(
    const hf* __restrict__ A, const hf* __restrict__ Bm,
    hf* __restrict__ outp) {
    extern __shared__ char smx[];
    uint32_t sb = smem_u32(smx);
    int tid = threadIdx.x, wid = tid >> 5, lane = tid & 31;
    int bm = blockIdx.y * 128, bn = blockIdx.x * 128;
    int wm = (wid & 3) * 32, wn = (wid >> 2) * 64;
    const int K = D_;

    float acc[2][8][4];
#pragma unroll
    for (int i = 0; i < 2; i++)
#pragma unroll
        for (int j = 0; j < 8; j++)
#pragma unroll
            for (int t = 0; t < 4; t++) acc[i][j][t] = 0.f;

    gemm_mainloop(sb, tid, A + (size_t)bm * K, Bm + (size_t)bn * K, K, acc);

#pragma unroll
    for (int mt = 0; mt < 2; mt++) {
        int m0 = bm + wm + mt * 16 + (lane >> 2);
#pragma unroll
        for (int nt = 0; nt < 8; nt++) {
            int f0 = (bn + wn + nt * 8 + (lane & 3) * 2) >> 1;
#pragma unroll
            for (int rr = 0; rr < 2; rr++) {
                int m = m0 + rr * 8;
                float u = acc[mt][nt][rr * 2];
                float g = acc[mt][nt][rr * 2 + 1];
                float r = u * (1.0f / (1.0f + __expf(-u))) * g;
                outp[(size_t)m * DFF_ + f0] = __float2half_rn(r);
            }
        }
    }
}

// ---------------------------------------------------------------------------
// RoPE table (double precision)
// ---------------------------------------------------------------------------
__global__ void rope_table_kernel(float2* __restrict__ tab) {
    int idx = blockIdx.x * blockDim.x + threadIdx.x;
    if (idx >= S_ * 32) return;
    int s = idx >> 5;
    int i = idx & 31;
    double invf = exp2(-(double)(2 * i) * (13.287712379549449 / 64.0));
    double ang = (double)s * invf;
    double sd, cd;
    sincos(ang, &sd, &cd);
    tab[idx] = make_float2((float)cd, (float)sd);
}

// ---------------------------------------------------------------------------
// RMSNorm -> single fp16
// ---------------------------------------------------------------------------
__global__ __launch_bounds__(256) void rmsnorm_h_kernel(
    const float* __restrict__ x, const float* __restrict__ w,
    hf* __restrict__ out) {
    int row = blockIdx.x;
    const float4* xr = (const float4*)(x + (size_t)row * D_);
    int i = threadIdx.x;
    float4 xv = xr[i];
    float ss = xv.x * xv.x + xv.y * xv.y + xv.z * xv.z + xv.w * xv.w;
#pragma unroll
    for (int off = 16; off > 0; off >>= 1)
        ss += __shfl_xor_sync(0xffffffffu, ss, off);
    __shared__ float red[8];
    __shared__ float s_inv;
    if ((threadIdx.x & 31) == 0) red[threadIdx.x >> 5] = ss;
    __syncthreads();
    if (threadIdx.x == 0) {
        float t = 0.f;
#pragma unroll
        for (int j = 0; j < 8; j++) t += red[j];
        s_inv = rsqrtf(t * (1.0f / D_) + 1e-5f);
    }
    __syncthreads();
    float inv = s_inv;
    float4 wv = ((const float4*)w)[i];
    uint2 o;
    o.x = packh2(inv * xv.x * wv.x, inv * xv.y * wv.y);
    o.y = packh2(inv * xv.z * wv.z, inv * xv.w * wv.w);
    ((uint2*)(out + (size_t)row * D_))[i] = o;
}

// ---------------------------------------------------------------------------
// HMMA causal flash attention (bf16 split internals); writes single fp16
// ---------------------------------------------------------------------------
#define AP    144
#define SQH   0
#define SQL   9216
#define SKH   18432
#define SKL   27648
#define SVH   36864
#define SVL   46080
#define AT_SMEM 55296

__global__ __launch_bounds__(128, 2) void attn_mma_kernel(
    const __nv_bfloat16* __restrict__ sh_in, const __nv_bfloat16* __restrict__ sl_in,
    hf* __restrict__ oh) {
    extern __shared__ char smx[];
    uint32_t sb = smem_u32(smx);
    int tid = threadIdx.x, w = tid >> 5, lane = tid & 31;
    int qt = gridDim.x - 1 - blockIdx.x;
    int h = blockIdx.y, b = blockIdx.z;
    size_t base = (size_t)(b * H_ + h) * S_;
    int s0 = qt * 64;

    const __nv_bfloat16* qh = sh_in + OQ_;
    const __nv_bfloat16* ql = sl_in + OQ_;
    const __nv_bfloat16* kh = sh_in + OK_;
    const __nv_bfloat16* kl = sl_in + OK_;
    const __nv_bfloat16* vh = sh_in + OV_;
    const __nv_bfloat16* vl = sl_in + OV_;

#pragma unroll
    for (int i = 0; i < 4; i++) {
        int idx = i * 128 + tid;
        int row = idx >> 3, c = idx & 7;
        size_t go = (base + s0 + row) * DK_ + c * 8;
        cp16(sb + SQH + row * AP + c * 16, qh + go);
        cp16(sb + SQL + row * AP + c * 16, ql + go);
    }
    asm volatile("cp.async.commit_group;");
    asm volatile("cp.async.wait_group 0;");
    __syncthreads();

    uint32_t qfh[4][4], qfl[4][4];
#pragma unroll
    for (int ks = 0; ks < 4; ks++) {
        uint32_t ar = sb + SQH + (16 * w + (lane & 15)) * AP
                    + (ks * 16 + (lane >> 4) * 8) * 2;
        ldm4(qfh[ks], ar);
        ldm4(qfl[ks], ar + (SQL - SQH));
    }

    float oacc[8][4];
#pragma unroll
    for (int j = 0; j < 8; j++)
#pragma unroll
        for (int t = 0; t < 4; t++) oacc[j][t] = 0.f;
    float m0 = -INFINITY, m1 = -INFINITY, l0 = 0.f, l1 = 0.f;
    int q0 = s0 + 16 * w + (lane >> 2);

    for (int kvt = 0; kvt <= qt; kvt++) {
        int kv0 = kvt * 64;
        __syncthreads();
#pragma unroll
        for (int i = 0; i < 4; i++) {
            int idx = i * 128 + tid;
            int row = idx >> 3, c = idx & 7;
            size_t go = (base + kv0 + row) * DK_ + c * 8;
            uint32_t db = sb + row * AP + c * 16;
            cp16(db + SKH, kh + go);
            cp16(db + SKL, kl + go);
            cp16(db + SVH, vh + go);
            cp16(db + SVL, vl + go);
        }
        asm volatile("cp.async.commit_group;");
        asm volatile("cp.async.wait_group 0;");
        __syncthreads();

        float sacc[8][4];
#pragma unroll
        for (int j = 0; j < 8; j++)
#pragma unroll
            for (int t = 0; t < 4; t++) sacc[j][t] = 0.f;
#pragma unroll
        for (int ks = 0; ks < 4; ks++) {
            uint32_t br = sb + SKH + ((lane & 7) + ((lane >> 4) & 1) * 8) * AP
                        + (ks * 16 + ((lane >> 3) & 1) * 8) * 2;
#pragma unroll
            for (int g = 0; g < 4; g++) {
                uint32_t bh4[4], bl4[4];
                ldm4(bh4, br + g * 16 * AP);
                ldm4(bl4, br + g * 16 * AP + (SKL - SKH));
                mma16816(sacc[2 * g],     qfh[ks], bh4[0], bh4[1]);
                mma16816(sacc[2 * g + 1], qfh[ks], bh4[2], bh4[3]);
                mma16816(sacc[2 * g],     qfh[ks], bl4[0], bl4[1]);
                mma16816(sacc[2 * g + 1], qfh[ks], bl4[2], bl4[3]);
                mma16816(sacc[2 * g],     qfl[ks], bh4[0], bh4[1]);
                mma16816(sacc[2 * g + 1], qfl[ks], bh4[2], bh4[3]);
            }
        }
#pragma unroll
        for (int j = 0; j < 8; j++)
#pragma unroll
            for (int t = 0; t < 4; t++) sacc[j][t] *= 0.125f;
        if (kvt == qt) {
            int cb = kv0 + 2 * (lane & 3);
#pragma unroll
            for (int j = 0; j < 8; j++) {
                int kc = cb + 8 * j;
                if (kc     > q0)     sacc[j][0] = -INFINITY;
                if (kc + 1 > q0)     sacc[j][1] = -INFINITY;
                if (kc     > q0 + 8) sacc[j][2] = -INFINITY;
                if (kc + 1 > q0 + 8) sacc[j][3] = -INFINITY;
            }
        }
        float mx0 = -INFINITY, mx1 = -INFINITY;
#pragma unroll
        for (int j = 0; j < 8; j++) {
            mx0 = fmaxf(mx0, fmaxf(sacc[j][0], sacc[j][1]));
            mx1 = fmaxf(mx1, fmaxf(sacc[j][2], sacc[j][3]));
        }
        mx0 = fmaxf(mx0, __shfl_xor_sync(0xffffffffu, mx0, 1));
        mx0 = fmaxf(mx0, __shfl_xor_sync(0xffffffffu, mx0, 2));
        mx1 = fmaxf(mx1, __shfl_xor_sync(0xffffffffu, mx1, 1));
        mx1 = fmaxf(mx1, __shfl_xor_sync(0xffffffffu, mx1, 2));
        float mn0 = fmaxf(m0, mx0), mn1 = fmaxf(m1, mx1);
        float cr0 = __expf(m0 - mn0), cr1 = __expf(m1 - mn1);
        l0 *= cr0; l1 *= cr1;
#pragma unroll
        for (int j = 0; j < 8; j++) {
            oacc[j][0] *= cr0; oacc[j][1] *= cr0;
            oacc[j][2] *= cr1; oacc[j][3] *= cr1;
        }
        uint32_t pf[4][4];
#pragma unroll
        for (int j = 0; j < 8; j++) {
            float p0 = __expf(sacc[j][0] - mn0);
            float p1 = __expf(sacc[j][1] - mn0);
            float p2 = __expf(sacc[j][2] - mn1);
            float p3 = __expf(sacc[j][3] - mn1);
            l0 += p0 + p1; l1 += p2 + p3;
            pf[j >> 1][(j & 1) * 2]     = packbf(p0, p1);
            pf[j >> 1][(j & 1) * 2 + 1] = packbf(p2, p3);
        }
        m0 = mn0; m1 = mn1;
#pragma unroll
        for (int kt = 0; kt < 4; kt++) {
            uint32_t va = sb + SVH + (kt * 16 + (lane & 15)) * AP
                        + ((lane >> 4) * 8) * 2;
#pragma unroll
            for (int gn = 0; gn < 4; gn++) {
                uint32_t vb[4];
                ldm4t(vb, va + gn * 32);
                mma16816(oacc[2 * gn],     pf[kt], vb[0], vb[1]);
                mma16816(oacc[2 * gn + 1], pf[kt], vb[2], vb[3]);
                ldm4t(vb, va + gn * 32 + (SVL - SVH));
                mma16816(oacc[2 * gn],     pf[kt], vb[0], vb[1]);
                mma16816(oacc[2 * gn + 1], pf[kt], vb[2], vb[3]);
            }
        }
    }

    l0 += __shfl_xor_sync(0xffffffffu, l0, 1);
    l0 += __shfl_xor_sync(0xffffffffu, l0, 2);
    l1 += __shfl_xor_sync(0xffffffffu, l1, 1);
    l1 += __shfl_xor_sync(0xffffffffu, l1, 2);
    float i0 = 1.f / l0, i1 = 1.f / l1;

    size_t r0 = (size_t)(b * S_ + q0) * D_ + h * DK_;
    size_t r1 = (size_t)(b * S_ + q0 + 8) * D_ + h * DK_;
#pragma unroll
    for (int j = 0; j < 8; j++) {
        int dk0 = 8 * j + 2 * (lane & 3);
        *(uint32_t*)(oh + r0 + dk0) = packh2(oacc[j][0] * i0, oacc[j][1] * i0);
        *(uint32_t*)(oh + r1 + dk0) = packh2(oacc[j][2] * i1, oacc[j][3] * i1);
    }
}

// ---------------------------------------------------------------------------
// Launch (launch index 3 == qkv GEMM, targeted by ncu -s 5 -c 1)
// ---------------------------------------------------------------------------
extern "C" void kernel_launch(void* const* d_in, const int* in_sizes, int n_in,
                              void* d_out, int out_size) {
    const float* x   = (const float*)d_in[0];
    const float* w_q = (const float*)d_in[1];
    const float* w_k = (const float*)d_in[2];
    const float* w_v = (const float*)d_in[3];
    const float* w_o = (const float*)d_in[4];
    const float* ln1 = (const float*)d_in[5];
    const float* ln2 = (const float*)d_in[6];
    const float* w1  = (const float*)d_in[7];
    const float* w2  = (const float*)d_in[8];
    const float* w3  = (const float*)d_in[9];
    float* out = (float*)d_out;

    float *ffn, *x2;
    float2* rope;
    __nv_bfloat16 *sh, *sl;
    hf* wp;
    cudaGetSymbolAddress((void**)&ffn,  g_ffn);
    cudaGetSymbolAddress((void**)&x2,   g_x2);
    cudaGetSymbolAddress((void**)&rope, g_rope);
    cudaGetSymbolAddress((void**)&sh,   g_sh);
    cudaGetSymbolAddress((void**)&sl,   g_sl);
    cudaGetSymbolAddress((void**)&wp,   g_w);
    hf* hA    = (hf*)(sh + OA_);
    hf* h2A   = (hf*)sh;
    hf* siluA = (hf*)ffn;

    cudaFuncSetAttribute(mma_gemm_kernel,
                         cudaFuncAttributeMaxDynamicSharedMemorySize, MG_SMEM);
    cudaFuncSetAttribute(mma_gemm_qkv_kernel,
                         cudaFuncAttributeMaxDynamicSharedMemorySize, MG_SMEM);
    cudaFuncSetAttribute(mma_gemm_swiglu_kernel,
                         cudaFuncAttributeMaxDynamicSharedMemorySize, MG_SMEM);
    cudaFuncSetAttribute(attn_mma_kernel,
                         cudaFuncAttributeMaxDynamicSharedMemorySize, AT_SMEM);

    // 0..2
    rope_table_kernel<<<(S_ * 32 + 255) / 256, 256>>>(rope);
    rmsnorm_h_kernel<<<M_, 256>>>(x, ln1, hA);
    wconv3_kernel<<<1024, 256>>>(w_q, w_k, w_v, wp + OW_Q);

    // 3 (ncu target): qkv GEMM -> roped/split q,k,v
    mma_gemm_qkv_kernel<<<dim3(3072 / 128, M_ / 128), 256, MG_SMEM>>>(
        hA, wp + OW_Q, rope, sh, sl);

    // remaining weight converts
    wconv_kernel<<<256, 256>>>(w_o, wp + OW_O, 262144);
    wconv13_kernel<<<4096, 256>>>(w1, w3, wp + OW_1);
    wconv_kernel<<<1024, 256>>>(w2, wp + OW_2, 1048576);

    // attention -> fp16 at OA_
    attn_mma_kernel<<<dim3(S_ / 64, H_, B_), 128, AT_SMEM>>>(sh, sl, hA);

    // x2 = x + attn @ w_o^T
    mma_gemm_kernel<<<dim3(D_ / 128, M_ / 128), 256, MG_SMEM>>>(
        hA, wp + OW_O, x, x2, M_, D_, D_);

    // h2 = rmsnorm(x2)
    rmsnorm_h_kernel<<<M_, 256>>>(x2, ln2, h2A);

    // [u|g] GEMM + SwiGLU
    mma_gemm_swiglu_kernel<<<dim3(8192 / 128, M_ / 128), 256, MG_SMEM>>>(
        h2A, wp + OW_1, siluA);

    // out = x2 + silu @ w2^T
    mma_gemm_kernel<<<dim3(D_ / 128, M_ / 128), 256, MG_SMEM>>>(
        siluA, wp + OW_2, x2, out, M_, D_, DFF_);
}

// round 11
// speedup vs baseline: 2.0458x; 1.0133x over previous
#include <cuda_runtime.h>
#include <cuda_bf16.h>
#include <cuda_fp16.h>
#include <math.h>
#include <stdint.h>

#define B_   2
#define S_   2048
#define D_   1024
#define H_   16
#define DK_  64
#define DFF_ 4096
#define M_   (B_ * S_)

typedef __half hf;

// ---------------------------------------------------------------------------
// Scratch
// ---------------------------------------------------------------------------
__device__ float g_ffn[M_ * 2 * DFF_];   // reused as fp16 silu storage
__device__ float g_x2 [M_ * D_];
__device__ float2 g_rope[S_ * 32];

#define ASZ (16u * 1048576u)
#define WSZ (16u * 1048576u)
__device__ __nv_bfloat16 g_sh[ASZ];   // bf16 q/k/v hi + fp16 activation regions
__device__ __nv_bfloat16 g_sl[ASZ];   // bf16 q/k/v lo
__device__ hf g_w [WSZ];              // fp16 weights

// weight offsets; Q,K,V contiguous; W1,W3 interleaved at OW_1
#define OW_Q  0u
#define OW_O  3145728u
#define OW_1  4194304u
#define OW_2  12582912u
// activation regions in g_sh/g_sl
#define OQ_   0u
#define OK_   4194304u
#define OV_   8388608u
#define OA_   12582912u

// ---------------------------------------------------------------------------
// helpers
// ---------------------------------------------------------------------------
__device__ __forceinline__ uint32_t smem_u32(const void* p) {
    uint32_t a;
    asm("{ .reg .u64 t; cvta.to.shared.u64 t, %1; cvt.u32.u64 %0, t; }"
        : "=r"(a) : "l"(p));
    return a;
}
__device__ __forceinline__ void cp16(uint32_t dst, const void* src) {
    asm volatile("cp.async.cg.shared.global [%0], [%1], 16;"
                 :: "r"(dst), "l"(src));
}
__device__ __forceinline__ void ldm4(uint32_t* r, uint32_t a) {
    asm volatile("ldmatrix.sync.aligned.m8n8.x4.shared.b16 {%0,%1,%2,%3}, [%4];"
                 : "=r"(r[0]), "=r"(r[1]), "=r"(r[2]), "=r"(r[3]) : "r"(a));
}
__device__ __forceinline__ void ldm4t(uint32_t* r, uint32_t a) {
    asm volatile("ldmatrix.sync.aligned.m8n8.x4.trans.shared.b16 {%0,%1,%2,%3}, [%4];"
                 : "=r"(r[0]), "=r"(r[1]), "=r"(r[2]), "=r"(r[3]) : "r"(a));
}
__device__ __forceinline__ void mma16816(float* c, const uint32_t* a,
                                         uint32_t b0, uint32_t b1) {
    asm volatile(
        "mma.sync.aligned.m16n8k16.row.col.f32.bf16.bf16.f32 "
        "{%0,%1,%2,%3}, {%4,%5,%6,%7}, {%8,%9}, {%0,%1,%2,%3};"
        : "+f"(c[0]), "+f"(c[1]), "+f"(c[2]), "+f"(c[3])
        : "r"(a[0]), "r"(a[1]), "r"(a[2]), "r"(a[3]), "r"(b0), "r"(b1));
}
__device__ __forceinline__ void mmah(float* c, const uint32_t* a,
                                     uint32_t b0, uint32_t b1) {
    asm volatile(
        "mma.sync.aligned.m16n8k16.row.col.f32.f16.f16.f32 "
        "{%0,%1,%2,%3}, {%4,%5,%6,%7}, {%8,%9}, {%0,%1,%2,%3};"
        : "+f"(c[0]), "+f"(c[1]), "+f"(c[2]), "+f"(c[3])
        : "r"(a[0]), "r"(a[1]), "r"(a[2]), "r"(a[3]), "r"(b0), "r"(b1));
}
__device__ __forceinline__ uint32_t packbf(float lo, float hi) {
    uint32_t r;
    asm("cvt.rn.bf16x2.f32 %0, %1, %2;" : "=r"(r) : "f"(hi), "f"(lo));
    return r;
}
__device__ __forceinline__ uint32_t packh2(float lo, float hi) {
    uint32_t r;
    asm("cvt.rn.f16x2.f32 %0, %1, %2;" : "=r"(r) : "f"(hi), "f"(lo));
    return r;
}
__device__ __forceinline__ void split1(float v, float& rh, float& rl) {
    __nv_bfloat16 hb = __float2bfloat16(v);
    rh = __bfloat162float(hb);
    rl = v - rh;
}
__device__ __forceinline__ uint2 cvt4h(const float4 v) {
    uint2 u;
    u.x = packh2(v.x, v.y);
    u.y = packh2(v.z, v.w);
    return u;
}

// ---------------------------------------------------------------------------
// weight converts (fp32 -> fp16)
// ---------------------------------------------------------------------------
__global__ void wconv3_kernel(const float* __restrict__ a,
                              const float* __restrict__ b,
                              const float* __restrict__ c,
                              hf* __restrict__ o) {
    int t = blockIdx.x * blockDim.x + threadIdx.x;
    if (t >= 262144) return;
    ((uint2*)o)[t]          = cvt4h(((const float4*)a)[t]);
    ((uint2*)o)[262144 + t] = cvt4h(((const float4*)b)[t]);
    ((uint2*)o)[524288 + t] = cvt4h(((const float4*)c)[t]);
}

__global__ void wconv_kernel(const float* __restrict__ s, hf* __restrict__ o, int n4) {
    int q = n4 >> 2;
    int t = blockIdx.x * blockDim.x + threadIdx.x;
    if (t >= q) return;
#pragma unroll
    for (int i = 0; i < 4; i++)
        ((uint2*)o)[t + i * q] = cvt4h(((const float4*)s)[t + i * q]);
}

__global__ void wconv13_kernel(const float* __restrict__ w1,
                               const float* __restrict__ w3,
                               hf* __restrict__ o) {
    int t = blockIdx.x * blockDim.x + threadIdx.x;
    if (t >= DFF_ * D_ / 4) return;
    int i = t >> 8, c = t & 255;
    ((uint2*)o)[(2 * i) * 256 + c]     = cvt4h(((const float4*)w1)[t]);
    ((uint2*)o)[(2 * i + 1) * 256 + c] = cvt4h(((const float4*)w3)[t]);
}

// ---------------------------------------------------------------------------
// single-pass fp16 GEMM mainloop, BK=64 staging:
// stage layout: A0 | B0 | A1 | B1 (each 128 rows x 32 halves @ 80B pitch)
// 2-stage cp.async double buffer; 4 ks-steps and 2 barriers per stage.
// ---------------------------------------------------------------------------
#define LDSP    80
#define ARRSZ   10240
#define HALFSZ  20480          // A|B for one 32-wide k-half
#define STAGE   40960          // two k-halves
#define MG_SMEM (2 * STAGE)

__device__ __forceinline__ void gemm_mainloop(
    uint32_t sb, int tid,
    const hf* pA, const hf* pB,
    int K, float acc[2][8][4]) {
    int wid = tid >> 5, lane = tid & 31;
    int wm = (wid & 3) * 32, wn = (wid >> 2) * 64;
    int nch = K >> 6;
    int jrow0 = tid >> 2;
    int jrow1 = 64 + jrow0;
    int kb = (tid & 3);

#define LOADCHUNK(c, s)                                                        \
    {                                                                          \
        int k0 = (c) << 6;                                                     \
        uint32_t stg = sb + (s) * STAGE;                                       \
        _Pragma("unroll")                                                      \
        for (int hh2 = 0; hh2 < 2; hh2++) {                                    \
            uint32_t hb = stg + hh2 * HALFSZ;                                  \
            {                                                                  \
                uint32_t db = hb + jrow0 * LDSP + kb * 16;                     \
                size_t go = (size_t)jrow0 * K + k0 + hh2 * 32 + kb * 8;        \
                cp16(db, pA + go);                                             \
                cp16(db + ARRSZ, pB + go);                                     \
            }                                                                  \
            {                                                                  \
                uint32_t db = hb + jrow1 * LDSP + kb * 16;                     \
                size_t go = (size_t)jrow1 * K + k0 + hh2 * 32 + kb * 8;        \
                cp16(db, pA + go);                                             \
                cp16(db + ARRSZ, pB + go);                                     \
            }                                                                  \
        }                                                                      \
        asm volatile("cp.async.commit_group;");                                \
    }

    LOADCHUNK(0, 0)

    for (int c = 0; c < nch; c++) {
        int s = c & 1;
        if (c + 1 < nch) {
            LOADCHUNK(c + 1, s ^ 1)
            asm volatile("cp.async.wait_group 1;");
        } else {
            asm volatile("cp.async.wait_group 0;");
        }
        __syncthreads();

        uint32_t stg = sb + s * STAGE;
#pragma unroll
        for (int hh2 = 0; hh2 < 2; hh2++) {
            uint32_t hb = stg + hh2 * HALFSZ;
#pragma unroll
            for (int ks = 0; ks < 2; ks++) {
                uint32_t ar = hb + (wm + (lane & 15)) * LDSP
                            + (ks * 16 + (lane >> 4) * 8) * 2;
                uint32_t af[2][4];
                ldm4(af[0], ar);
                ldm4(af[1], ar + 16 * LDSP);
                uint32_t br = hb + ARRSZ
                            + (wn + (lane & 7) + ((lane >> 4) & 1) * 8) * LDSP
                            + (ks * 16 + ((lane >> 3) & 1) * 8) * 2;
#pragma unroll
                for (int g = 0; g < 4; g++) {
                    uint32_t b4[4];
                    ldm4(b4, br + g * 16 * LDSP);
                    mmah(acc[0][2 * g],     af[0], b4[0], b4[1]);
                    mmah(acc[0][2 * g + 1], af[0], b4[2], b4[3]);
                    mmah(acc[1][2 * g],     af[1], b4[0], b4[1]);
                    mmah(acc[1][2 * g + 1], af[1], b4[2], b4[3]);
                }
            }
        }
        __syncthreads();
    }
}

// ---------------------------------------------------------------------------
// generic GEMM: C fp32 (+R)
// ---------------------------------------------------------------------------
__global__ __launch_bounds__(256, 2) void mma_gemm_kernel(
    const hf* __restrict__ A, const hf* __restrict__ Bm,
    const float* __restrict__ R, float* __restrict__ C,
    int M, int N, int K) {
    extern __shared__ char smx[];
    uint32_t sb = smem_u32(smx);
    int tid = threadIdx.x, wid = tid >> 5, lane = tid & 31;
    int bm = blockIdx.y * 128, bn = blockIdx.x * 128;
    int wm = (wid & 3) * 32, wn = (wid >> 2) * 64;

    float acc[2][8][4];
#pragma unroll
    for (int i = 0; i < 2; i++)
#pragma unroll
        for (int j = 0; j < 8; j++)
#pragma unroll
            for (int t = 0; t < 4; t++) acc[i][j][t] = 0.f;

    gemm_mainloop(sb, tid, A + (size_t)bm * K, Bm + (size_t)bn * K, K, acc);

#pragma unroll
    for (int mt = 0; mt < 2; mt++) {
        int m0 = bm + wm + mt * 16 + (lane >> 2);
#pragma unroll
        for (int nt = 0; nt < 8; nt++) {
            int n0 = bn + wn + nt * 8 + (lane & 3) * 2;
            float2 v0 = make_float2(acc[mt][nt][0], acc[mt][nt][1]);
            float2 v1 = make_float2(acc[mt][nt][2], acc[mt][nt][3]);
            if (R) {
                float2 r0 = *(const float2*)(R + (size_t)m0 * N + n0);
                float2 r1 = *(const float2*)(R + (size_t)(m0 + 8) * N + n0);
                v0.x += r0.x; v0.y += r0.y;
                v1.x += r1.x; v1.y += r1.y;
            }
            *(float2*)(C + (size_t)m0 * N + n0) = v0;
            *(float2*)(C + (size_t)(m0 + 8) * N + n0) = v1;
        }
    }
}

// ---------------------------------------------------------------------------
// qkv GEMM (N=3072): epilogue RoPE + bf16 hi/lo split + [b,h,s,dk] repack
// ---------------------------------------------------------------------------
__global__ __launch_bounds__(256, 2) void mma_gemm_qkv_kernel(
    const hf* __restrict__ A, const hf* __restrict__ Bm,
    const float2* __restrict__ tab,
    __nv_bfloat16* __restrict__ osh, __nv_bfloat16* __restrict__ osl) {
    extern __shared__ char smx[];
    uint32_t sb = smem_u32(smx);
    int tid = threadIdx.x, wid = tid >> 5, lane = tid & 31;
    int bm = blockIdx.y * 128, bn = blockIdx.x * 128;
    int wm = (wid & 3) * 32, wn = (wid >> 2) * 64;
    const int K = D_;

    float acc[2][8][4];
#pragma unroll
    for (int i = 0; i < 2; i++)
#pragma unroll
        for (int j = 0; j < 8; j++)
#pragma unroll
            for (int t = 0; t < 4; t++) acc[i][j][t] = 0.f;

    gemm_mainloop(sb, tid, A + (size_t)bm * K, Bm + (size_t)bn * K, K, acc);

#pragma unroll
    for (int nt = 0; nt < 8; nt++) {
        int n0 = bn + wn + nt * 8 + (lane & 3) * 2;
        int sec = n0 >> 10;
        int d = n0 & 1023;
        int hh = d >> 6;
        int dk = d & 63;
        uint32_t obase = sec * 4194304u;
#pragma unroll
        for (int mt = 0; mt < 2; mt++) {
            int m0 = bm + wm + mt * 16 + (lane >> 2);
#pragma unroll
            for (int rr = 0; rr < 2; rr++) {
                int m = m0 + rr * 8;
                int s = m & (S_ - 1);
                int b = m >> 11;
                float e = acc[mt][nt][rr * 2], o = acc[mt][nt][rr * 2 + 1];
                if (sec < 2) {
                    float2 cs = tab[(s << 5) + (dk >> 1)];
                    float e2 = cs.x * e - cs.y * o;
                    o = cs.y * e + cs.x * o;
                    e = e2;
                }
                float eh, el, oh2, ol2;
                split1(e, eh, el); split1(o, oh2, ol2);
                size_t off = obase + ((size_t)(b * H_ + hh) * S_ + s) * DK_ + dk;
                *(uint32_t*)(osh + off) = packbf(eh, oh2);
                *(uint32_t*)(osl + off) = packbf(el, ol2);
            }
        }
    }
}

// ---------------------------------------------------------------------------
// w1|w3 GEMM + SwiGLU: N=8192 interleaved (even=u, odd=g); writes fp16 silu
// ---------------------------------------------------------------------------
__global__ __launch_bounds__(256, 2) void mma_gemm_swiglu_kernel(
    const hf* __restrict__ A, const hf* __restrict__ Bm,
    hf* __restrict__ outp) {
    extern __shared__ char smx[];
    uint32_t sb = smem_u32(smx);
    int tid = threadIdx.x, wid = tid >> 5, lane = tid & 31;
    int bm = blockIdx.y * 128, bn = blockIdx.x * 128;
    int wm = (wid & 3) * 32, wn = (wid >> 2) * 64;
    const int K = D_;

    float acc[2][8][4];
#pragma unroll
    for (int i = 0; i < 2; i++)
#pragma unroll
        for (int j = 0; j < 8; j++)
#pragma unroll
            for (int t = 0; t < 4; t++) acc[i][j][t] = 0.f;

    gemm_mainloop(sb, tid, A + (size_t)bm * K, Bm + (size_t)bn * K, K, acc);

#pragma unroll
    for (int mt = 0; mt < 2; mt++) {
        int m0 = bm + wm + mt * 16 + (lane >> 2);
#pragma unroll
        for (int nt = 0; nt < 8; nt++) {
            int f0 = (bn + wn + nt * 8 + (lane & 3) * 2) >> 1;
#pragma unroll
            for (int rr = 0; rr < 2; rr++) {
                int m = m0 + rr * 8;
                float u = acc[mt][nt][rr * 2];
                float g = acc[mt][nt][rr * 2 + 1];
                float r = u * (1.0f / (1.0f + __expf(-u))) * g;
                outp[(size_t)m * DFF_ + f0] = __float2half_rn(r);
            }
        }
    }
}

// ---------------------------------------------------------------------------
// RoPE table (double precision)
// ---------------------------------------------------------------------------
__global__ void rope_table_kernel(float2* __restrict__ tab) {
    int idx = blockIdx.x * blockDim.x + threadIdx.x;
    if (idx >= S_ * 32) return;
    int s = idx >> 5;
    int i = idx & 31;
    double invf = exp2(-(double)(2 * i) * (13.287712379549449 / 64.0));
    double ang = (double)s * invf;
    double sd, cd;
    sincos(ang, &sd, &cd);
    tab[idx] = make_float2((float)cd, (float)sd);
}

// ---------------------------------------------------------------------------
// RMSNorm -> single fp16
// ---------------------------------------------------------------------------
__global__ __launch_bounds__(256) void rmsnorm_h_kernel(
    const float* __restrict__ x, const float* __restrict__ w,
    hf* __restrict__ out) {
    int row = blockIdx.x;
    const float4* xr = (const float4*)(x + (size_t)row * D_);
    int i = threadIdx.x;
    float4 xv = xr[i];
    float ss = xv.x * xv.x + xv.y * xv.y + xv.z * xv.z + xv.w * xv.w;
#pragma unroll
    for (int off = 16; off > 0; off >>= 1)
        ss += __shfl_xor_sync(0xffffffffu, ss, off);
    __shared__ float red[8];
    __shared__ float s_inv;
    if ((threadIdx.x & 31) == 0) red[threadIdx.x >> 5] = ss;
    __syncthreads();
    if (threadIdx.x == 0) {
        float t = 0.f;
#pragma unroll
        for (int j = 0; j < 8; j++) t += red[j];
        s_inv = rsqrtf(t * (1.0f / D_) + 1e-5f);
    }
    __syncthreads();
    float inv = s_inv;
    float4 wv = ((const float4*)w)[i];
    uint2 o;
    o.x = packh2(inv * xv.x * wv.x, inv * xv.y * wv.y);
    o.y = packh2(inv * xv.z * wv.z, inv * xv.w * wv.w);
    ((uint2*)(out + (size_t)row * D_))[i] = o;
}

// ---------------------------------------------------------------------------
// HMMA causal flash attention (bf16 split internals); writes single fp16
// ---------------------------------------------------------------------------
#define AP    144
#define SQH   0
#define SQL   9216
#define SKH   18432
#define SKL   27648
#define SVH   36864
#define SVL   46080
#define AT_SMEM 55296

__global__ __launch_bounds__(128, 2) void attn_mma_kernel(
    const __nv_bfloat16* __restrict__ sh_in, const __nv_bfloat16* __restrict__ sl_in,
    hf* __restrict__ oh) {
    extern __shared__ char smx[];
    uint32_t sb = smem_u32(smx);
    int tid = threadIdx.x, w = tid >> 5, lane = tid & 31;
    int qt = gridDim.x - 1 - blockIdx.x;
    int h = blockIdx.y, b = blockIdx.z;
    size_t base = (size_t)(b * H_ + h) * S_;
    int s0 = qt * 64;

    const __nv_bfloat16* qh = sh_in + OQ_;
    const __nv_bfloat16* ql = sl_in + OQ_;
    const __nv_bfloat16* kh = sh_in + OK_;
    const __nv_bfloat16* kl = sl_in + OK_;
    const __nv_bfloat16* vh = sh_in + OV_;
    const __nv_bfloat16* vl = sl_in + OV_;

#pragma unroll
    for (int i = 0; i < 4; i++) {
        int idx = i * 128 + tid;
        int row = idx >> 3, c = idx & 7;
        size_t go = (base + s0 + row) * DK_ + c * 8;
        cp16(sb + SQH + row * AP + c * 16, qh + go);
        cp16(sb + SQL + row * AP + c * 16, ql + go);
    }
    asm volatile("cp.async.commit_group;");
    asm volatile("cp.async.wait_group 0;");
    __syncthreads();

    uint32_t qfh[4][4], qfl[4][4];
#pragma unroll
    for (int ks = 0; ks < 4; ks++) {
        uint32_t ar = sb + SQH + (16 * w + (lane & 15)) * AP
                    + (ks * 16 + (lane >> 4) * 8) * 2;
        ldm4(qfh[ks], ar);
        ldm4(qfl[ks], ar + (SQL - SQH));
    }

    float oacc[8][4];
#pragma unroll
    for (int j = 0; j < 8; j++)
#pragma unroll
        for (int t = 0; t < 4; t++) oacc[j][t] = 0.f;
    float m0 = -INFINITY, m1 = -INFINITY, l0 = 0.f, l1 = 0.f;
    int q0 = s0 + 16 * w + (lane >> 2);

    for (int kvt = 0; kvt <= qt; kvt++) {
        int kv0 = kvt * 64;
        __syncthreads();
#pragma unroll
        for (int i = 0; i < 4; i++) {
            int idx = i * 128 + tid;
            int row = idx >> 3, c = idx & 7;
            size_t go = (base + kv0 + row) * DK_ + c * 8;
            uint32_t db = sb + row * AP + c * 16;
            cp16(db + SKH, kh + go);
            cp16(db + SKL, kl + go);
            cp16(db + SVH, vh + go);
            cp16(db + SVL, vl + go);
        }
        asm volatile("cp.async.commit_group;");
        asm volatile("cp.async.wait_group 0;");
        __syncthreads();

        float sacc[8][4];
#pragma unroll
        for (int j = 0; j < 8; j++)
#pragma unroll
            for (int t = 0; t < 4; t++) sacc[j][t] = 0.f;
#pragma unroll
        for (int ks = 0; ks < 4; ks++) {
            uint32_t br = sb + SKH + ((lane & 7) + ((lane >> 4) & 1) * 8) * AP
                        + (ks * 16 + ((lane >> 3) & 1) * 8) * 2;
#pragma unroll
            for (int g = 0; g < 4; g++) {
                uint32_t bh4[4], bl4[4];
                ldm4(bh4, br + g * 16 * AP);
                ldm4(bl4, br + g * 16 * AP + (SKL - SKH));
                mma16816(sacc[2 * g],     qfh[ks], bh4[0], bh4[1]);
                mma16816(sacc[2 * g + 1], qfh[ks], bh4[2], bh4[3]);
                mma16816(sacc[2 * g],     qfh[ks], bl4[0], bl4[1]);
                mma16816(sacc[2 * g + 1], qfh[ks], bl4[2], bl4[3]);
                mma16816(sacc[2 * g],     qfl[ks], bh4[0], bh4[1]);
                mma16816(sacc[2 * g + 1], qfl[ks], bh4[2], bh4[3]);
            }
        }
#pragma unroll
        for (int j = 0; j < 8; j++)
#pragma unroll
            for (int t = 0; t < 4; t++) sacc[j][t] *= 0.125f;
        if (kvt == qt) {
            int cb = kv0 + 2 * (lane & 3);
#pragma unroll
            for (int j = 0; j < 8; j++) {
                int kc = cb + 8 * j;
                if (kc     > q0)     sacc[j][0] = -INFINITY;
                if (kc + 1 > q0)     sacc[j][1] = -INFINITY;
                if (kc     > q0 + 8) sacc[j][2] = -INFINITY;
                if (kc + 1 > q0 + 8) sacc[j][3] = -INFINITY;
            }
        }
        float mx0 = -INFINITY, mx1 = -INFINITY;
#pragma unroll
        for (int j = 0; j < 8; j++) {
            mx0 = fmaxf(mx0, fmaxf(sacc[j][0], sacc[j][1]));
            mx1 = fmaxf(mx1, fmaxf(sacc[j][2], sacc[j][3]));
        }
        mx0 = fmaxf(mx0, __shfl_xor_sync(0xffffffffu, mx0, 1));
        mx0 = fmaxf(mx0, __shfl_xor_sync(0xffffffffu, mx0, 2));
        mx1 = fmaxf(mx1, __shfl_xor_sync(0xffffffffu, mx1, 1));
        mx1 = fmaxf(mx1, __shfl_xor_sync(0xffffffffu, mx1, 2));
        float mn0 = fmaxf(m0, mx0), mn1 = fmaxf(m1, mx1);
        float cr0 = __expf(m0 - mn0), cr1 = __expf(m1 - mn1);
        l0 *= cr0; l1 *= cr1;
#pragma unroll
        for (int j = 0; j < 8; j++) {
            oacc[j][0] *= cr0; oacc[j][1] *= cr0;
            oacc[j][2] *= cr1; oacc[j][3] *= cr1;
        }
        uint32_t pf[4][4];
#pragma unroll
        for (int j = 0; j < 8; j++) {
            float p0 = __expf(sacc[j][0] - mn0);
            float p1 = __expf(sacc[j][1] - mn0);
            float p2 = __expf(sacc[j][2] - mn1);
            float p3 = __expf(sacc[j][3] - mn1);
            l0 += p0 + p1; l1 += p2 + p3;
            pf[j >> 1][(j & 1) * 2]     = packbf(p0, p1);
            pf[j >> 1][(j & 1) * 2 + 1] = packbf(p2, p3);
        }
        m0 = mn0; m1 = mn1;
#pragma unroll
        for (int kt = 0; kt < 4; kt++) {
            uint32_t va = sb + SVH + (kt * 16 + (lane & 15)) * AP
                        + ((lane >> 4) * 8) * 2;
#pragma unroll
            for (int gn = 0; gn < 4; gn++) {
                uint32_t vb[4];
                ldm4t(vb, va + gn * 32);
                mma16816(oacc[2 * gn],     pf[kt], vb[0], vb[1]);
                mma16816(oacc[2 * gn + 1], pf[kt], vb[2], vb[3]);
                ldm4t(vb, va + gn * 32 + (SVL - SVH));
                mma16816(oacc[2 * gn],     pf[kt], vb[0], vb[1]);
                mma16816(oacc[2 * gn + 1], pf[kt], vb[2], vb[3]);
            }
        }
    }

    l0 += __shfl_xor_sync(0xffffffffu, l0, 1);
    l0 += __shfl_xor_sync(0xffffffffu, l0, 2);
    l1 += __shfl_xor_sync(0xffffffffu, l1, 1);
    l1 += __shfl_xor_sync(0xffffffffu, l1, 2);
    float i0 = 1.f / l0, i1 = 1.f / l1;

    size_t r0 = (size_t)(b * S_ + q0) * D_ + h * DK_;
    size_t r1 = (size_t)(b * S_ + q0 + 8) * D_ + h * DK_;
#pragma unroll
    for (int j = 0; j < 8; j++) {
        int dk0 = 8 * j + 2 * (lane & 3);
        *(uint32_t*)(oh + r0 + dk0) = packh2(oacc[j][0] * i0, oacc[j][1] * i0);
        *(uint32_t*)(oh + r1 + dk0) = packh2(oacc[j][2] * i1, oacc[j][3] * i1);
    }
}

// ---------------------------------------------------------------------------
// Launch (launch index 3 == qkv GEMM, targeted by ncu -s 5 -c 1)
// ---------------------------------------------------------------------------
extern "C" void kernel_launch(void* const* d_in, const int* in_sizes, int n_in,
                              void* d_out, int out_size) {
    const float* x   = (const float*)d_in[0];
    const float* w_q = (const float*)d_in[1];
    const float* w_k = (const float*)d_in[2];
    const float* w_v = (const float*)d_in[3];
    const float* w_o = (const float*)d_in[4];
    const float* ln1 = (const float*)d_in[5];
    const float* ln2 = (const float*)d_in[6];
    const float* w1  = (const float*)d_in[7];
    const float* w2  = (const float*)d_in[8];
    const float* w3  = (const float*)d_in[9];
    float* out = (float*)d_out;

    float *ffn, *x2;
    float2* rope;
    __nv_bfloat16 *sh, *sl;
    hf* wp;
    cudaGetSymbolAddress((void**)&ffn,  g_ffn);
    cudaGetSymbolAddress((void**)&x2,   g_x2);
    cudaGetSymbolAddress((void**)&rope, g_rope);
    cudaGetSymbolAddress((void**)&sh,   g_sh);
    cudaGetSymbolAddress((void**)&sl,   g_sl);
    cudaGetSymbolAddress((void**)&wp,   g_w);
    hf* hA    = (hf*)(sh + OA_);
    hf* h2A   = (hf*)sh;
    hf* siluA = (hf*)ffn;

    cudaFuncSetAttribute(mma_gemm_kernel,
                         cudaFuncAttributeMaxDynamicSharedMemorySize, MG_SMEM);
    cudaFuncSetAttribute(mma_gemm_qkv_kernel,
                         cudaFuncAttributeMaxDynamicSharedMemorySize, MG_SMEM);
    cudaFuncSetAttribute(mma_gemm_swiglu_kernel,
                         cudaFuncAttributeMaxDynamicSharedMemorySize, MG_SMEM);
    cudaFuncSetAttribute(attn_mma_kernel,
                         cudaFuncAttributeMaxDynamicSharedMemorySize, AT_SMEM);

    // 0..2
    rope_table_kernel<<<(S_ * 32 + 255) / 256, 256>>>(rope);
    rmsnorm_h_kernel<<<M_, 256>>>(x, ln1, hA);
    wconv3_kernel<<<1024, 256>>>(w_q, w_k, w_v, wp + OW_Q);

    // 3 (ncu target): qkv GEMM -> roped/split q,k,v
    mma_gemm_qkv_kernel<<<dim3(3072 / 128, M_ / 128), 256, MG_SMEM>>>(
        hA, wp + OW_Q, rope, sh, sl);

    // remaining weight converts
    wconv_kernel<<<256, 256>>>(w_o, wp + OW_O, 262144);
    wconv13_kernel<<<4096, 256>>>(w1, w3, wp + OW_1);
    wconv_kernel<<<1024, 256>>>(w2, wp + OW_2, 1048576);

    // attention -> fp16 at OA_
    attn_mma_kernel<<<dim3(S_ / 64, H_, B_), 128, AT_SMEM>>>(sh, sl, hA);

    // x2 = x + attn @ w_o^T
    mma_gemm_kernel<<<dim3(D_ / 128, M_ / 128), 256, MG_SMEM>>>(
        hA, wp + OW_O, x, x2, M_, D_, D_);

    // h2 = rmsnorm(x2)
    rmsnorm_h_kernel<<<M_, 256>>>(x2, ln2, h2A);

    // [u|g] GEMM + SwiGLU
    mma_gemm_swiglu_kernel<<<dim3(8192 / 128, M_ / 128), 256, MG_SMEM>>>(
        h2A, wp + OW_1, siluA);

    // out = x2 + silu @ w2^T
    mma_gemm_kernel<<<dim3(D_ / 128, M_ / 128), 256, MG_SMEM>>>(
        siluA, wp + OW_2, x2, out, M_, D_, DFF_);
}

// round 12
// speedup vs baseline: 2.3210x; 1.1345x over previous
#include <cuda_runtime.h>
#include <cuda_bf16.h>
#include <cuda_fp16.h>
#include <math.h>
#include <stdint.h>

#define B_   2
#define S_   2048
#define D_   1024
#define H_   16
#define DK_  64
#define DFF_ 4096
#define M_   (B_ * S_)

typedef __half hf;

// ---------------------------------------------------------------------------
// Scratch
// ---------------------------------------------------------------------------
__device__ float g_ffn[M_ * 2 * DFF_];   // reused as fp16 silu storage
__device__ float g_x2 [M_ * D_];
__device__ float2 g_rope[S_ * 32];

#define ASZ (16u * 1048576u)
#define WSZ (16u * 1048576u)
__device__ __nv_bfloat16 g_sh[ASZ];   // fp16 activation regions (q,k,v,h,attn)
__device__ __nv_bfloat16 g_sl[ASZ];   // spare
__device__ hf g_w [WSZ];              // fp16 weights

// weight offsets; Q,K,V contiguous; W1,W3 interleaved at OW_1
#define OW_Q  0u
#define OW_O  3145728u
#define OW_1  4194304u
#define OW_2  12582912u
// activation regions (element offsets, 2B elems)
#define OQ_   0u
#define OK_   4194304u
#define OV_   8388608u
#define OA_   12582912u

// ---------------------------------------------------------------------------
// helpers
// ---------------------------------------------------------------------------
__device__ __forceinline__ uint32_t smem_u32(const void* p) {
    uint32_t a;
    asm("{ .reg .u64 t; cvta.to.shared.u64 t, %1; cvt.u32.u64 %0, t; }"
        : "=r"(a) : "l"(p));
    return a;
}
__device__ __forceinline__ void cp16(uint32_t dst, const void* src) {
    asm volatile("cp.async.cg.shared.global [%0], [%1], 16;"
                 :: "r"(dst), "l"(src));
}
__device__ __forceinline__ void ldm4(uint32_t* r, uint32_t a) {
    asm volatile("ldmatrix.sync.aligned.m8n8.x4.shared.b16 {%0,%1,%2,%3}, [%4];"
                 : "=r"(r[0]), "=r"(r[1]), "=r"(r[2]), "=r"(r[3]) : "r"(a));
}
__device__ __forceinline__ void ldm4t(uint32_t* r, uint32_t a) {
    asm volatile("ldmatrix.sync.aligned.m8n8.x4.trans.shared.b16 {%0,%1,%2,%3}, [%4];"
                 : "=r"(r[0]), "=r"(r[1]), "=r"(r[2]), "=r"(r[3]) : "r"(a));
}
__device__ __forceinline__ void mmah(float* c, const uint32_t* a,
                                     uint32_t b0, uint32_t b1) {
    asm volatile(
        "mma.sync.aligned.m16n8k16.row.col.f32.f16.f16.f32 "
        "{%0,%1,%2,%3}, {%4,%5,%6,%7}, {%8,%9}, {%0,%1,%2,%3};"
        : "+f"(c[0]), "+f"(c[1]), "+f"(c[2]), "+f"(c[3])
        : "r"(a[0]), "r"(a[1]), "r"(a[2]), "r"(a[3]), "r"(b0), "r"(b1));
}
__device__ __forceinline__ uint32_t packh2(float lo, float hi) {
    uint32_t r;
    asm("cvt.rn.f16x2.f32 %0, %1, %2;" : "=r"(r) : "f"(hi), "f"(lo));
    return r;
}
__device__ __forceinline__ uint2 cvt4h(const float4 v) {
    uint2 u;
    u.x = packh2(v.x, v.y);
    u.y = packh2(v.z, v.w);
    return u;
}

// ---------------------------------------------------------------------------
// weight converts (fp32 -> fp16)
// ---------------------------------------------------------------------------
__global__ void wconv3_kernel(const float* __restrict__ a,
                              const float* __restrict__ b,
                              const float* __restrict__ c,
                              hf* __restrict__ o) {
    int t = blockIdx.x * blockDim.x + threadIdx.x;
    if (t >= 262144) return;
    ((uint2*)o)[t]          = cvt4h(((const float4*)a)[t]);
    ((uint2*)o)[262144 + t] = cvt4h(((const float4*)b)[t]);
    ((uint2*)o)[524288 + t] = cvt4h(((const float4*)c)[t]);
}

__global__ void wconv_kernel(const float* __restrict__ s, hf* __restrict__ o, int n4) {
    int q = n4 >> 2;
    int t = blockIdx.x * blockDim.x + threadIdx.x;
    if (t >= q) return;
#pragma unroll
    for (int i = 0; i < 4; i++)
        ((uint2*)o)[t + i * q] = cvt4h(((const float4*)s)[t + i * q]);
}

__global__ void wconv13_kernel(const float* __restrict__ w1,
                               const float* __restrict__ w3,
                               hf* __restrict__ o) {
    int t = blockIdx.x * blockDim.x + threadIdx.x;
    if (t >= DFF_ * D_ / 4) return;
    int i = t >> 8, c = t & 255;
    ((uint2*)o)[(2 * i) * 256 + c]     = cvt4h(((const float4*)w1)[t]);
    ((uint2*)o)[(2 * i + 1) * 256 + c] = cvt4h(((const float4*)w3)[t]);
}

// ---------------------------------------------------------------------------
// single-pass fp16 GEMM mainloop, BK=64 staging (unchanged from R11)
// ---------------------------------------------------------------------------
#define LDSP    80
#define ARRSZ   10240
#define HALFSZ  20480
#define STAGE   40960
#define MG_SMEM (2 * STAGE)

__device__ __forceinline__ void gemm_mainloop(
    uint32_t sb, int tid,
    const hf* pA, const hf* pB,
    int K, float acc[2][8][4]) {
    int wid = tid >> 5, lane = tid & 31;
    int wm = (wid & 3) * 32, wn = (wid >> 2) * 64;
    int nch = K >> 6;
    int jrow0 = tid >> 2;
    int jrow1 = 64 + jrow0;
    int kb = (tid & 3);

#define LOADCHUNK(c, s)                                                        \
    {                                                                          \
        int k0 = (c) << 6;                                                     \
        uint32_t stg = sb + (s) * STAGE;                                       \
        _Pragma("unroll")                                                      \
        for (int hh2 = 0; hh2 < 2; hh2++) {                                    \
            uint32_t hb = stg + hh2 * HALFSZ;                                  \
            {                                                                  \
                uint32_t db = hb + jrow0 * LDSP + kb * 16;                     \
                size_t go = (size_t)jrow0 * K + k0 + hh2 * 32 + kb * 8;        \
                cp16(db, pA + go);                                             \
                cp16(db + ARRSZ, pB + go);                                     \
            }                                                                  \
            {                                                                  \
                uint32_t db = hb + jrow1 * LDSP + kb * 16;                     \
                size_t go = (size_t)jrow1 * K + k0 + hh2 * 32 + kb * 8;        \
                cp16(db, pA + go);                                             \
                cp16(db + ARRSZ, pB + go);                                     \
            }                                                                  \
        }                                                                      \
        asm volatile("cp.async.commit_group;");                                \
    }

    LOADCHUNK(0, 0)

    for (int c = 0; c < nch; c++) {
        int s = c & 1;
        if (c + 1 < nch) {
            LOADCHUNK(c + 1, s ^ 1)
            asm volatile("cp.async.wait_group 1;");
        } else {
            asm volatile("cp.async.wait_group 0;");
        }
        __syncthreads();

        uint32_t stg = sb + s * STAGE;
#pragma unroll
        for (int hh2 = 0; hh2 < 2; hh2++) {
            uint32_t hb = stg + hh2 * HALFSZ;
#pragma unroll
            for (int ks = 0; ks < 2; ks++) {
                uint32_t ar = hb + (wm + (lane & 15)) * LDSP
                            + (ks * 16 + (lane >> 4) * 8) * 2;
                uint32_t af[2][4];
                ldm4(af[0], ar);
                ldm4(af[1], ar + 16 * LDSP);
                uint32_t br = hb + ARRSZ
                            + (wn + (lane & 7) + ((lane >> 4) & 1) * 8) * LDSP
                            + (ks * 16 + ((lane >> 3) & 1) * 8) * 2;
#pragma unroll
                for (int g = 0; g < 4; g++) {
                    uint32_t b4[4];
                    ldm4(b4, br + g * 16 * LDSP);
                    mmah(acc[0][2 * g],     af[0], b4[0], b4[1]);
                    mmah(acc[0][2 * g + 1], af[0], b4[2], b4[3]);
                    mmah(acc[1][2 * g],     af[1], b4[0], b4[1]);
                    mmah(acc[1][2 * g + 1], af[1], b4[2], b4[3]);
                }
            }
        }
        __syncthreads();
    }
}

// ---------------------------------------------------------------------------
// generic GEMM: C fp32 (+R)
// ---------------------------------------------------------------------------
__global__ __launch_bounds__(256, 2) void mma_gemm_kernel(
    const hf* __restrict__ A, const hf* __restrict__ Bm,
    const float* __restrict__ R, float* __restrict__ C,
    int M, int N, int K) {
    extern __shared__ char smx[];
    uint32_t sb = smem_u32(smx);
    int tid = threadIdx.x, wid = tid >> 5, lane = tid & 31;
    int bm = blockIdx.y * 128, bn = blockIdx.x * 128;
    int wm = (wid & 3) * 32, wn = (wid >> 2) * 64;

    float acc[2][8][4];
#pragma unroll
    for (int i = 0; i < 2; i++)
#pragma unroll
        for (int j = 0; j < 8; j++)
#pragma unroll
            for (int t = 0; t < 4; t++) acc[i][j][t] = 0.f;

    gemm_mainloop(sb, tid, A + (size_t)bm * K, Bm + (size_t)bn * K, K, acc);

#pragma unroll
    for (int mt = 0; mt < 2; mt++) {
        int m0 = bm + wm + mt * 16 + (lane >> 2);
#pragma unroll
        for (int nt = 0; nt < 8; nt++) {
            int n0 = bn + wn + nt * 8 + (lane & 3) * 2;
            float2 v0 = make_float2(acc[mt][nt][0], acc[mt][nt][1]);
            float2 v1 = make_float2(acc[mt][nt][2], acc[mt][nt][3]);
            if (R) {
                float2 r0 = *(const float2*)(R + (size_t)m0 * N + n0);
                float2 r1 = *(const float2*)(R + (size_t)(m0 + 8) * N + n0);
                v0.x += r0.x; v0.y += r0.y;
                v1.x += r1.x; v1.y += r1.y;
            }
            *(float2*)(C + (size_t)m0 * N + n0) = v0;
            *(float2*)(C + (size_t)(m0 + 8) * N + n0) = v1;
        }
    }
}

// ---------------------------------------------------------------------------
// qkv GEMM (N=3072): epilogue RoPE + single-fp16 write + [b,h,s,dk] repack
// ---------------------------------------------------------------------------
__global__ __launch_bounds__(256, 2) void mma_gemm_qkv_kernel(
    const hf* __restrict__ A, const hf* __restrict__ Bm,
    const float2* __restrict__ tab,
    hf* __restrict__ oq) {
    extern __shared__ char smx[];
    uint32_t sb = smem_u32(smx);
    int tid = threadIdx.x, wid = tid >> 5, lane = tid & 31;
    int bm = blockIdx.y * 128, bn = blockIdx.x * 128;
    int wm = (wid & 3) * 32, wn = (wid >> 2) * 64;
    const int K = D_;

    float acc[2][8][4];
#pragma unroll
    for (int i = 0; i < 2; i++)
#pragma unroll
        for (int j = 0; j < 8; j++)
#pragma unroll
            for (int t = 0; t < 4; t++) acc[i][j][t] = 0.f;

    gemm_mainloop(sb, tid, A + (size_t)bm * K, Bm + (size_t)bn * K, K, acc);

#pragma unroll
    for (int nt = 0; nt < 8; nt++) {
        int n0 = bn + wn + nt * 8 + (lane & 3) * 2;
        int sec = n0 >> 10;
        int d = n0 & 1023;
        int hh = d >> 6;
        int dk = d & 63;
        uint32_t obase = sec * 4194304u;
#pragma unroll
        for (int mt = 0; mt < 2; mt++) {
            int m0 = bm + wm + mt * 16 + (lane >> 2);
#pragma unroll
            for (int rr = 0; rr < 2; rr++) {
                int m = m0 + rr * 8;
                int s = m & (S_ - 1);
                int b = m >> 11;
                float e = acc[mt][nt][rr * 2], o = acc[mt][nt][rr * 2 + 1];
                if (sec < 2) {
                    float2 cs = tab[(s << 5) + (dk >> 1)];
                    float e2 = cs.x * e - cs.y * o;
                    o = cs.y * e + cs.x * o;
                    e = e2;
                }
                size_t off = obase + ((size_t)(b * H_ + hh) * S_ + s) * DK_ + dk;
                *(uint32_t*)(oq + off) = packh2(e, o);
            }
        }
    }
}

// ---------------------------------------------------------------------------
// w1|w3 GEMM + SwiGLU: N=8192 interleaved (even=u, odd=g); writes fp16 silu
// ---------------------------------------------------------------------------
__global__ __launch_bounds__(256, 2) void mma_gemm_swiglu_kernel(
    const hf* __restrict__ A, const hf* __restrict__ Bm,
    hf* __restrict__ outp) {
    extern __shared__ char smx[];
    uint32_t sb = smem_u32(smx);
    int tid = threadIdx.x, wid = tid >> 5, lane = tid & 31;
    int bm = blockIdx.y * 128, bn = blockIdx.x * 128;
    int wm = (wid & 3) * 32, wn = (wid >> 2) * 64;
    const int K = D_;

    float acc[2][8][4];
#pragma unroll
    for (int i = 0; i < 2; i++)
#pragma unroll
        for (int j = 0; j < 8; j++)
#pragma unroll
            for (int t = 0; t < 4; t++) acc[i][j][t] = 0.f;

    gemm_mainloop(sb, tid, A + (size_t)bm * K, Bm + (size_t)bn * K, K, acc);

#pragma unroll
    for (int mt = 0; mt < 2; mt++) {
        int m0 = bm + wm + mt * 16 + (lane >> 2);
#pragma unroll
        for (int nt = 0; nt < 8; nt++) {
            int f0 = (bn + wn + nt * 8 + (lane & 3) * 2) >> 1;
#pragma unroll
            for (int rr = 0; rr < 2; rr++) {
                int m = m0 + rr * 8;
                float u = acc[mt][nt][rr * 2];
                float g = acc[mt][nt][rr * 2 + 1];
                float r = u * (1.0f / (1.0f + __expf(-u))) * g;
                outp[(size_t)m * DFF_ + f0] = __float2half_rn(r);
            }
        }
    }
}

// ---------------------------------------------------------------------------
// RoPE table (double precision)
// ---------------------------------------------------------------------------
__global__ void rope_table_kernel(float2* __restrict__ tab) {
    int idx = blockIdx.x * blockDim.x + threadIdx.x;
    if (idx >= S_ * 32) return;
    int s = idx >> 5;
    int i = idx & 31;
    double invf = exp2(-(double)(2 * i) * (13.287712379549449 / 64.0));
    double ang = (double)s * invf;
    double sd, cd;
    sincos(ang, &sd, &cd);
    tab[idx] = make_float2((float)cd, (float)sd);
}

// ---------------------------------------------------------------------------
// RMSNorm -> single fp16
// ---------------------------------------------------------------------------
__global__ __launch_bounds__(256) void rmsnorm_h_kernel(
    const float* __restrict__ x, const float* __restrict__ w,
    hf* __restrict__ out) {
    int row = blockIdx.x;
    const float4* xr = (const float4*)(x + (size_t)row * D_);
    int i = threadIdx.x;
    float4 xv = xr[i];
    float ss = xv.x * xv.x + xv.y * xv.y + xv.z * xv.z + xv.w * xv.w;
#pragma unroll
    for (int off = 16; off > 0; off >>= 1)
        ss += __shfl_xor_sync(0xffffffffu, ss, off);
    __shared__ float red[8];
    __shared__ float s_inv;
    if ((threadIdx.x & 31) == 0) red[threadIdx.x >> 5] = ss;
    __syncthreads();
    if (threadIdx.x == 0) {
        float t = 0.f;
#pragma unroll
        for (int j = 0; j < 8; j++) t += red[j];
        s_inv = rsqrtf(t * (1.0f / D_) + 1e-5f);
    }
    __syncthreads();
    float inv = s_inv;
    float4 wv = ((const float4*)w)[i];
    uint2 o;
    o.x = packh2(inv * xv.x * wv.x, inv * xv.y * wv.y);
    o.y = packh2(inv * xv.z * wv.z, inv * xv.w * wv.w);
    ((uint2*)(out + (size_t)row * D_))[i] = o;
}

// ---------------------------------------------------------------------------
// Single-fp16 HMMA causal flash attention, 2-stage KV cp.async pipeline.
// Grid (S/64, H, B), 128 threads (4 warps x 16 q rows).
// ---------------------------------------------------------------------------
#define AP     144
#define ATQ    0
#define ATKV   9216               // K(s)=ATKV+s*18432, V(s)=K(s)+9216
#define AT_SMEM (9216 + 2 * 18432)

__global__ __launch_bounds__(128, 3) void attn_mma_kernel(
    const hf* __restrict__ qg, const hf* __restrict__ kg,
    const hf* __restrict__ vg, hf* __restrict__ oh) {
    extern __shared__ char smx[];
    uint32_t sb = smem_u32(smx);
    int tid = threadIdx.x, w = tid >> 5, lane = tid & 31;
    int qt = gridDim.x - 1 - blockIdx.x;
    int h = blockIdx.y, b = blockIdx.z;
    size_t base = (size_t)(b * H_ + h) * S_;
    int s0 = qt * 64;

    // Q tile load (own group)
#pragma unroll
    for (int i = 0; i < 4; i++) {
        int idx = i * 128 + tid;
        int row = idx >> 3, c = idx & 7;
        cp16(sb + ATQ + row * AP + c * 16, qg + (base + s0 + row) * DK_ + c * 8);
    }
    asm volatile("cp.async.commit_group;");

#define LOADKV(t, s)                                                           \
    {                                                                          \
        uint32_t kvb = sb + ATKV + (s) * 18432;                                \
        _Pragma("unroll")                                                      \
        for (int i = 0; i < 4; i++) {                                          \
            int idx = i * 128 + tid;                                           \
            int row = idx >> 3, c = idx & 7;                                   \
            size_t go = (base + (t) * 64 + row) * DK_ + c * 8;                 \
            cp16(kvb + row * AP + c * 16, kg + go);                            \
            cp16(kvb + 9216 + row * AP + c * 16, vg + go);                     \
        }                                                                      \
        asm volatile("cp.async.commit_group;");                                \
    }

    LOADKV(0, 0)
    asm volatile("cp.async.wait_group 1;");   // Q done
    __syncthreads();

    uint32_t qf[4][4];
#pragma unroll
    for (int ks = 0; ks < 4; ks++) {
        uint32_t ar = sb + ATQ + (16 * w + (lane & 15)) * AP
                    + (ks * 16 + (lane >> 4) * 8) * 2;
        ldm4(qf[ks], ar);
    }

    float oacc[8][4];
#pragma unroll
    for (int j = 0; j < 8; j++)
#pragma unroll
        for (int t = 0; t < 4; t++) oacc[j][t] = 0.f;
    float m0 = -INFINITY, m1 = -INFINITY, l0 = 0.f, l1 = 0.f;
    int q0 = s0 + 16 * w + (lane >> 2);

    for (int kvt = 0; kvt <= qt; kvt++) {
        int s = kvt & 1;
        if (kvt < qt) {
            LOADKV(kvt + 1, s ^ 1)
            asm volatile("cp.async.wait_group 1;");
        } else {
            asm volatile("cp.async.wait_group 0;");
        }
        __syncthreads();

        uint32_t kvb = sb + ATKV + s * 18432;
        float sacc[8][4];
#pragma unroll
        for (int j = 0; j < 8; j++)
#pragma unroll
            for (int t = 0; t < 4; t++) sacc[j][t] = 0.f;
#pragma unroll
        for (int ks = 0; ks < 4; ks++) {
            uint32_t br = kvb + ((lane & 7) + ((lane >> 4) & 1) * 8) * AP
                        + (ks * 16 + ((lane >> 3) & 1) * 8) * 2;
#pragma unroll
            for (int g = 0; g < 4; g++) {
                uint32_t b4[4];
                ldm4(b4, br + g * 16 * AP);
                mmah(sacc[2 * g],     qf[ks], b4[0], b4[1]);
                mmah(sacc[2 * g + 1], qf[ks], b4[2], b4[3]);
            }
        }
#pragma unroll
        for (int j = 0; j < 8; j++)
#pragma unroll
            for (int t = 0; t < 4; t++) sacc[j][t] *= 0.125f;
        if (kvt == qt) {
            int cb = kvt * 64 + 2 * (lane & 3);
#pragma unroll
            for (int j = 0; j < 8; j++) {
                int kc = cb + 8 * j;
                if (kc     > q0)     sacc[j][0] = -INFINITY;
                if (kc + 1 > q0)     sacc[j][1] = -INFINITY;
                if (kc     > q0 + 8) sacc[j][2] = -INFINITY;
                if (kc + 1 > q0 + 8) sacc[j][3] = -INFINITY;
            }
        }
        float mx0 = -INFINITY, mx1 = -INFINITY;
#pragma unroll
        for (int j = 0; j < 8; j++) {
            mx0 = fmaxf(mx0, fmaxf(sacc[j][0], sacc[j][1]));
            mx1 = fmaxf(mx1, fmaxf(sacc[j][2], sacc[j][3]));
        }
        mx0 = fmaxf(mx0, __shfl_xor_sync(0xffffffffu, mx0, 1));
        mx0 = fmaxf(mx0, __shfl_xor_sync(0xffffffffu, mx0, 2));
        mx1 = fmaxf(mx1, __shfl_xor_sync(0xffffffffu, mx1, 1));
        mx1 = fmaxf(mx1, __shfl_xor_sync(0xffffffffu, mx1, 2));
        float mn0 = fmaxf(m0, mx0), mn1 = fmaxf(m1, mx1);
        float cr0 = __expf(m0 - mn0), cr1 = __expf(m1 - mn1);
        l0 *= cr0; l1 *= cr1;
#pragma unroll
        for (int j = 0; j < 8; j++) {
            oacc[j][0] *= cr0; oacc[j][1] *= cr0;
            oacc[j][2] *= cr1; oacc[j][3] *= cr1;
        }
        uint32_t pf[4][4];
#pragma unroll
        for (int j = 0; j < 8; j++) {
            float p0 = __expf(sacc[j][0] - mn0);
            float p1 = __expf(sacc[j][1] - mn0);
            float p2 = __expf(sacc[j][2] - mn1);
            float p3 = __expf(sacc[j][3] - mn1);
            l0 += p0 + p1; l1 += p2 + p3;
            pf[j >> 1][(j & 1) * 2]     = packh2(p0, p1);
            pf[j >> 1][(j & 1) * 2 + 1] = packh2(p2, p3);
        }
        m0 = mn0; m1 = mn1;
#pragma unroll
        for (int kt = 0; kt < 4; kt++) {
            uint32_t va = kvb + 9216 + (kt * 16 + (lane & 15)) * AP
                        + ((lane >> 4) * 8) * 2;
#pragma unroll
            for (int gn = 0; gn < 4; gn++) {
                uint32_t vb[4];
                ldm4t(vb, va + gn * 32);
                mmah(oacc[2 * gn],     pf[kt], vb[0], vb[1]);
                mmah(oacc[2 * gn + 1], pf[kt], vb[2], vb[3]);
            }
        }
        __syncthreads();
    }

    l0 += __shfl_xor_sync(0xffffffffu, l0, 1);
    l0 += __shfl_xor_sync(0xffffffffu, l0, 2);
    l1 += __shfl_xor_sync(0xffffffffu, l1, 1);
    l1 += __shfl_xor_sync(0xffffffffu, l1, 2);
    float i0 = 1.f / l0, i1 = 1.f / l1;

    size_t r0 = (size_t)(b * S_ + q0) * D_ + h * DK_;
    size_t r1 = (size_t)(b * S_ + q0 + 8) * D_ + h * DK_;
#pragma unroll
    for (int j = 0; j < 8; j++) {
        int dk0 = 8 * j + 2 * (lane & 3);
        *(uint32_t*)(oh + r0 + dk0) = packh2(oacc[j][0] * i0, oacc[j][1] * i0);
        *(uint32_t*)(oh + r1 + dk0) = packh2(oacc[j][2] * i1, oacc[j][3] * i1);
    }
}

// ---------------------------------------------------------------------------
// Launch (launch index 3 == qkv GEMM, targeted by ncu -s 5 -c 1)
// ---------------------------------------------------------------------------
extern "C" void kernel_launch(void* const* d_in, const int* in_sizes, int n_in,
                              void* d_out, int out_size) {
    const float* x   = (const float*)d_in[0];
    const float* w_q = (const float*)d_in[1];
    const float* w_k = (const float*)d_in[2];
    const float* w_v = (const float*)d_in[3];
    const float* w_o = (const float*)d_in[4];
    const float* ln1 = (const float*)d_in[5];
    const float* ln2 = (const float*)d_in[6];
    const float* w1  = (const float*)d_in[7];
    const float* w2  = (const float*)d_in[8];
    const float* w3  = (const float*)d_in[9];
    float* out = (float*)d_out;

    float *ffn, *x2;
    float2* rope;
    __nv_bfloat16 *sh;
    hf* wp;
    cudaGetSymbolAddress((void**)&ffn,  g_ffn);
    cudaGetSymbolAddress((void**)&x2,   g_x2);
    cudaGetSymbolAddress((void**)&rope, g_rope);
    cudaGetSymbolAddress((void**)&sh,   g_sh);
    cudaGetSymbolAddress((void**)&wp,   g_w);
    hf* qA    = (hf*)sh + OQ_;
    hf* kA    = (hf*)sh + OK_;
    hf* vA    = (hf*)sh + OV_;
    hf* hA    = (hf*)sh + OA_;         // h / attn-out region
    hf* h2A   = (hf*)sh;               // h2 (q region reusable after attn)
    hf* siluA = (hf*)ffn;

    cudaFuncSetAttribute(mma_gemm_kernel,
                         cudaFuncAttributeMaxDynamicSharedMemorySize, MG_SMEM);
    cudaFuncSetAttribute(mma_gemm_qkv_kernel,
                         cudaFuncAttributeMaxDynamicSharedMemorySize, MG_SMEM);
    cudaFuncSetAttribute(mma_gemm_swiglu_kernel,
                         cudaFuncAttributeMaxDynamicSharedMemorySize, MG_SMEM);
    cudaFuncSetAttribute(attn_mma_kernel,
                         cudaFuncAttributeMaxDynamicSharedMemorySize, AT_SMEM);

    // 0..2
    rope_table_kernel<<<(S_ * 32 + 255) / 256, 256>>>(rope);
    rmsnorm_h_kernel<<<M_, 256>>>(x, ln1, hA);
    wconv3_kernel<<<1024, 256>>>(w_q, w_k, w_v, wp + OW_Q);

    // 3 (ncu target): qkv GEMM -> roped fp16 q,k,v in [b,h,s,dk]
    mma_gemm_qkv_kernel<<<dim3(3072 / 128, M_ / 128), 256, MG_SMEM>>>(
        hA, wp + OW_Q, rope, (hf*)sh);

    // remaining weight converts
    wconv_kernel<<<256, 256>>>(w_o, wp + OW_O, 262144);
    wconv13_kernel<<<4096, 256>>>(w1, w3, wp + OW_1);
    wconv_kernel<<<1024, 256>>>(w2, wp + OW_2, 1048576);

    // attention -> fp16 at OA_ (overwrites h, already consumed)
    attn_mma_kernel<<<dim3(S_ / 64, H_, B_), 128, AT_SMEM>>>(qA, kA, vA, hA);

    // x2 = x + attn @ w_o^T
    mma_gemm_kernel<<<dim3(D_ / 128, M_ / 128), 256, MG_SMEM>>>(
        hA, wp + OW_O, x, x2, M_, D_, D_);

    // h2 = rmsnorm(x2)
    rmsnorm_h_kernel<<<M_, 256>>>(x2, ln2, h2A);

    // [u|g] GEMM + SwiGLU
    mma_gemm_swiglu_kernel<<<dim3(8192 / 128, M_ / 128), 256, MG_SMEM>>>(
        h2A, wp + OW_1, siluA);

    // out = x2 + silu @ w2^T
    mma_gemm_kernel<<<dim3(D_ / 128, M_ / 128), 256, MG_SMEM>>>(
        siluA, wp + OW_2, x2, out, M_, D_, DFF_);
}